// round 6
// baseline (speedup 1.0000x reference)
#include <cuda_runtime.h>
#include <math.h>
#include <stdint.h>

#define B_  8
#define T_  2048
#define C_  3
#define E_  256
#define K_  15
#define D_  5
#define BN_ 32
#define WSZ (BN_*BN_*K_)   // 15360 floats per mid layer

struct P3 { const float *q, *k, *v; };

__device__ __forceinline__ const float* pick(const P3& p, int net){
    return net==0 ? p.q : (net==1 ? p.k : p.v);
}

// ---------------- scratch (device globals; no allocs allowed) ----------------
static __device__ float g_mean[B_*C_];
static __device__ float g_std [B_*C_];
static __device__ float g_qn[B_*C_*T_];
static __device__ float g_kn[B_*C_*T_];
static __device__ float g_h0[3*B_*BN_*T_];
static __device__ float g_h1[3*B_*BN_*T_];
static __device__ float g_wt[3*D_*WSZ];           // mid weights transposed [net][layer][ci*15+k][cout]
static __device__ float g_qh[(size_t)B_*T_*E_];
static __device__ float g_ql[(size_t)B_*T_*E_];
static __device__ float g_kh[(size_t)B_*T_*E_];
static __device__ float g_kl[(size_t)B_*T_*E_];
static __device__ float g_vth[(size_t)B_*E_*T_];  // V transposed [B][E][T]
static __device__ float g_vtl[(size_t)B_*E_*T_];
static __device__ float g_attn[(size_t)B_*T_*T_]; // S raw (128 MiB)
static __device__ float g_ph[(size_t)B_*T_*T_];   // P split hi
static __device__ float g_pl[(size_t)B_*T_*T_];   // P split lo
static __device__ float g_o[(size_t)B_*T_*E_];

// ---------------- tf32 split ----------------
__device__ __forceinline__ void tfsplit(float x, float& h, float& l){
    unsigned hb; asm("cvt.rna.tf32.f32 %0, %1;" : "=r"(hb) : "f"(x));
    h = __uint_as_float(hb);
    float r = x - h;
    unsigned lb; asm("cvt.rna.tf32.f32 %0, %1;" : "=r"(lb) : "f"(r));
    l = __uint_as_float(lb);
}

// ---------------- RevIN stats over time of key_in ----------------
__global__ void k_stats(const float* __restrict__ key){
    int bc = blockIdx.x, b = bc / C_, c = bc % C_;
    int tid = threadIdx.x;
    float s = 0.f, ss = 0.f;
    for (int t = tid; t < T_; t += 256){
        float x = key[((size_t)b*T_ + t)*C_ + c];
        s += x; ss += x*x;
    }
    __shared__ float r1[256], r2[256];
    r1[tid]=s; r2[tid]=ss; __syncthreads();
    for(int o=128;o;o>>=1){ if(tid<o){ r1[tid]+=r1[tid+o]; r2[tid]+=r2[tid+o]; } __syncthreads(); }
    if(tid==0){
        float m = r1[0]/(float)T_;
        float v = r2[0]/(float)T_ - m*m;
        g_mean[bc]=m;
        g_std[bc]=sqrtf(v + 1e-5f);
    }
}

// ---------------- normalize + transpose to [B][C][T] ----------------
__global__ void k_norm(const float* __restrict__ q, const float* __restrict__ k,
                       const float* __restrict__ rw, const float* __restrict__ rb){
    int i = blockIdx.x*256 + threadIdx.x;
    if(i >= B_*C_*T_) return;
    int t = i % T_, c = (i / T_) % C_, b = i / (C_*T_);
    float m = g_mean[b*C_+c], inv = 1.f/g_std[b*C_+c];
    float w = rw[c], bb = rb[c];
    size_t src = ((size_t)b*T_ + t)*C_ + c;
    g_qn[i] = (q[src]-m)*inv*w + bb;
    g_kn[i] = (k[src]-m)*inv*w + bb;
}

// ---------------- transpose mid weights to [ci*15+k][cout] ----------------
__global__ void k_wtrans(P3 wm, float* __restrict__ wt){
    int layer = blockIdx.x, net = blockIdx.y;
    const float* src = pick(wm, net) + (size_t)layer*WSZ;
    float* dst = wt + ((size_t)(net*D_ + layer))*WSZ;
    for(int i=threadIdx.x; i<WSZ; i+=blockDim.x){
        int cout = i/480, rest = i - cout*480;
        dst[rest*BN_ + cout] = src[i];
    }
}

// ---------------- conv in (fused q/k/v): C_ -> BN_, K=15, dil=1, relu ------
__global__ void k_conv_in(const float* __restrict__ qn, const float* __restrict__ kn,
                          P3 w, P3 bias, float* __restrict__ dstbase){
    int net = blockIdx.z;
    const float* src = (net==0) ? qn : kn;
    const float* wp  = pick(w, net);
    const float* bp  = pick(bias, net);
    float* dst = dstbase + (size_t)net*B_*BN_*T_;

    __shared__ float ws[BN_*C_*K_];
    __shared__ float bs[BN_];
    __shared__ float xs[C_][256 + K_ - 1];
    int b = blockIdx.y, t0 = blockIdx.x*256, tid = threadIdx.x;
    for(int i=tid;i<BN_*C_*K_;i+=256) ws[i]=wp[i];
    if(tid<BN_) bs[tid]=bp[tid];
    const int W = 256 + K_ - 1;
    for(int i=tid;i<C_*W;i+=256){
        int ci=i/W, p=i%W, g=t0+p-7;
        xs[ci][p] = ((unsigned)g < T_) ? src[(b*C_+ci)*T_ + g] : 0.f;
    }
    __syncthreads();
    float acc[BN_];
    #pragma unroll
    for(int c=0;c<BN_;c++) acc[c]=bs[c];
    #pragma unroll
    for(int ci=0;ci<C_;ci++){
        #pragma unroll
        for(int k=0;k<K_;k++){
            float x = xs[ci][tid+k];
            #pragma unroll
            for(int c=0;c<BN_;c++) acc[c] += x * ws[(c*C_+ci)*K_+k];
        }
    }
    int t = t0 + tid;
    #pragma unroll
    for(int c=0;c<BN_;c++) dst[((size_t)b*BN_+c)*T_ + t] = fmaxf(acc[c], 0.f);
}

// ------- conv mid (fused q/k/v, cout split in halves): BN_->BN_, dilated ---
// x tile in smem only; transposed weights via uniform __ldg (L1-resident).
template<int DIL>
__global__ void k_conv_mid(const float* __restrict__ srcbase,
                           const float* __restrict__ wt, P3 bm,
                           float* __restrict__ dstbase, int layer){
    constexpr int W = 128 + 14*DIL;
    constexpr int H = 7*DIL;
    extern __shared__ float xs[];      // BN_ * W floats

    int net = blockIdx.z >> 1, half = blockIdx.z & 1;
    int co0 = half * 16;
    const float* w    = wt + ((size_t)(net*D_ + layer))*WSZ + co0;  // [ci*15+k][32]
    const float* bias = pick(bm, net) + layer*BN_ + co0;
    const float* src  = srcbase + (size_t)net*B_*BN_*T_;
    float* dst        = dstbase + (size_t)net*B_*BN_*T_;

    int b = blockIdx.y, t0 = blockIdx.x*128, tid = threadIdx.x;

    for(int i=tid;i<BN_*W;i+=128){
        int ci = i/W, p = i - ci*W, g = t0 - H + p;
        xs[i] = ((unsigned)g < T_) ? src[(b*BN_+ci)*T_ + g] : 0.f;
    }
    __syncthreads();

    float acc[16];
    #pragma unroll
    for(int c=0;c<16;c++) acc[c]=__ldg(&bias[c]);

    for(int ci=0;ci<BN_;ci++){
        const float* xr = xs + ci*W + tid;
        #pragma unroll
        for(int k=0;k<K_;k++){
            float x = xr[k*DIL];
            const float4* wr = (const float4*)(w + (ci*K_+k)*BN_);
            #pragma unroll
            for(int m=0;m<4;m++){
                float4 wv = __ldg(&wr[m]);
                acc[4*m+0] += x*wv.x;
                acc[4*m+1] += x*wv.y;
                acc[4*m+2] += x*wv.z;
                acc[4*m+3] += x*wv.w;
            }
        }
    }
    int t = t0 + tid;
    #pragma unroll
    for(int c=0;c<16;c++) dst[((size_t)b*BN_+co0+c)*T_ + t] = fmaxf(acc[c], 0.f);
}

// ------- conv out (fused, 1x1): BN_ -> E_, writes tf32-split Q/K/Vt -------
__global__ void k_conv_out(const float* __restrict__ srcbase, P3 w, P3 bias,
                           float* __restrict__ qh, float* __restrict__ ql,
                           float* __restrict__ kh, float* __restrict__ kl,
                           float* __restrict__ vth, float* __restrict__ vtl){
    int net = blockIdx.z;
    const float* src = srcbase + (size_t)net*B_*BN_*T_;
    const float* wp  = pick(w, net);
    const float* bp  = pick(bias, net);

    __shared__ float xs[BN_][32];
    int b = blockIdx.y, t0 = blockIdx.x*32, e = threadIdx.x;
    for(int i=e;i<BN_*32;i+=256){
        int ci=i>>5, tl=i&31;
        xs[ci][tl] = src[((size_t)b*BN_+ci)*T_ + t0 + tl];
    }
    __syncthreads();
    float acc[32];
    float bb = bp[e];
    #pragma unroll
    for(int t=0;t<32;t++) acc[t]=bb;
    #pragma unroll 4
    for(int ci=0;ci<BN_;ci++){
        float wv = __ldg(&wp[e*BN_+ci]);
        #pragma unroll
        for(int t=0;t<32;t++) acc[t] += xs[ci][t]*wv;
    }
    if(net < 2){
        float* H = net ? kh : qh;
        float* L = net ? kl : ql;
        #pragma unroll
        for(int t=0;t<32;t++){
            float h,l; tfsplit(acc[t], h, l);
            size_t o = ((size_t)b*T_ + t0+t)*E_ + e;
            H[o]=h; L[o]=l;
        }
    } else {
        size_t o = ((size_t)b*E_ + e)*T_ + t0;
        #pragma unroll
        for(int t=0;t<32;t++){
            float h,l; tfsplit(acc[t], h, l);
            vth[o+t]=h; vtl[o+t]=l;
        }
    }
}

// =================== 3xTF32 mma.sync GEMM, NT form, precomputed splits =====
__device__ __forceinline__ void mma8(float* c, const unsigned* a, unsigned b0, unsigned b1){
    asm volatile(
        "mma.sync.aligned.m16n8k8.row.col.f32.tf32.tf32.f32 "
        "{%0,%1,%2,%3},{%4,%5,%6,%7},{%8,%9},{%0,%1,%2,%3};"
        : "+f"(c[0]), "+f"(c[1]), "+f"(c[2]), "+f"(c[3])
        : "r"(a[0]), "r"(a[1]), "r"(a[2]), "r"(a[3]), "r"(b0), "r"(b1));
}

#define SKM 136   // padded smem leading dim

__device__ __forceinline__ void mma_chunk(
    const unsigned (*AsH)[SKM], const unsigned (*AsL)[SKM],
    const unsigned (*BsH)[SKM], const unsigned (*BsL)[SKM],
    float acc[16][4], int wm, int wn, int lane)
{
    int lq = lane >> 2, lr = lane & 3;
    #pragma unroll
    for(int ks=0; ks<2; ks++){
        int kb = ks*8 + lr;
        unsigned aH[2][4], aL[2][4];
        #pragma unroll
        for(int mt=0; mt<2; mt++){
            int rm = wm*32 + mt*16 + lq;
            aH[mt][0]=AsH[kb  ][rm];  aH[mt][1]=AsH[kb  ][rm+8];
            aH[mt][2]=AsH[kb+4][rm];  aH[mt][3]=AsH[kb+4][rm+8];
            aL[mt][0]=AsL[kb  ][rm];  aL[mt][1]=AsL[kb  ][rm+8];
            aL[mt][2]=AsL[kb+4][rm];  aL[mt][3]=AsL[kb+4][rm+8];
        }
        #pragma unroll
        for(int nt=0; nt<8; nt++){
            int cn = wn*64 + nt*8 + lq;
            unsigned bH0=BsH[kb][cn], bH1=BsH[kb+4][cn];
            unsigned bL0=BsL[kb][cn], bL1=BsL[kb+4][cn];
            #pragma unroll
            for(int mt=0; mt<2; mt++){
                mma8(acc[mt*8+nt], aH[mt], bH0, bH1);
                mma8(acc[mt*8+nt], aH[mt], bL0, bL1);
                mma8(acc[mt*8+nt], aL[mt], bH0, bH1);
            }
        }
    }
}

// C[M,N] = alpha * A[M,K] * B[N,K]^T  with A/B pre-split into hi/lo arrays
__global__ void __launch_bounds__(256)
k_mma_nt3(const float* __restrict__ Ah, const float* __restrict__ Al,
          const float* __restrict__ Bh, const float* __restrict__ Bl,
          float* __restrict__ Cm, int Kdim,
          size_t sA, size_t sB, size_t sC, int ldC, float alpha){
    __shared__ unsigned AsH[16][SKM], AsL[16][SKM], BsH[16][SKM], BsL[16][SKM];
    int bz = blockIdx.z;
    Ah += bz*sA; Al += bz*sA;
    Bh += bz*sB; Bl += bz*sB;
    Cm += bz*sC;
    int tid = threadIdx.x, lane = tid & 31, wid = tid >> 5;
    int wm = wid & 3, wn = wid >> 2;
    int row0 = blockIdx.x*128, col0 = blockIdx.y*128;

    float acc[16][4];
    #pragma unroll
    for(int i=0;i<16;i++){ acc[i][0]=acc[i][1]=acc[i][2]=acc[i][3]=0.f; }

    int r[2], c4[2];
    const float *pah[2], *pal[2], *pbh[2], *pbl[2];
    #pragma unroll
    for(int j=0;j<2;j++){
        int idx = tid + j*256;
        r[j] = idx>>2; c4[j] = (idx&3)<<2;
        size_t oa = (size_t)(row0+r[j])*Kdim + c4[j];
        size_t ob = (size_t)(col0+r[j])*Kdim + c4[j];
        pah[j] = Ah + oa; pal[j] = Al + oa;
        pbh[j] = Bh + ob; pbl[j] = Bl + ob;
    }
    float4 vah[2], val_[2], vbh[2], vbl[2];
    #pragma unroll
    for(int j=0;j<2;j++){
        vah[j] = *(const float4*)pah[j];  val_[j] = *(const float4*)pal[j];
        vbh[j] = *(const float4*)pbh[j];  vbl[j] = *(const float4*)pbl[j];
    }

    const int NCH = Kdim >> 4;
    for(int ch=0; ch<NCH; ch++){
        #pragma unroll
        for(int j=0;j<2;j++){
            int cc = c4[j], rr = r[j];
            AsH[cc+0][rr]=__float_as_uint(vah[j].x); AsH[cc+1][rr]=__float_as_uint(vah[j].y);
            AsH[cc+2][rr]=__float_as_uint(vah[j].z); AsH[cc+3][rr]=__float_as_uint(vah[j].w);
            AsL[cc+0][rr]=__float_as_uint(val_[j].x); AsL[cc+1][rr]=__float_as_uint(val_[j].y);
            AsL[cc+2][rr]=__float_as_uint(val_[j].z); AsL[cc+3][rr]=__float_as_uint(val_[j].w);
            BsH[cc+0][rr]=__float_as_uint(vbh[j].x); BsH[cc+1][rr]=__float_as_uint(vbh[j].y);
            BsH[cc+2][rr]=__float_as_uint(vbh[j].z); BsH[cc+3][rr]=__float_as_uint(vbh[j].w);
            BsL[cc+0][rr]=__float_as_uint(vbl[j].x); BsL[cc+1][rr]=__float_as_uint(vbl[j].y);
            BsL[cc+2][rr]=__float_as_uint(vbl[j].z); BsL[cc+3][rr]=__float_as_uint(vbl[j].w);
        }
        __syncthreads();
        if(ch+1 < NCH){
            int off = (ch+1)*16;
            #pragma unroll
            for(int j=0;j<2;j++){
                vah[j] = *(const float4*)(pah[j] + off);
                val_[j] = *(const float4*)(pal[j] + off);
                vbh[j] = *(const float4*)(pbh[j] + off);
                vbl[j] = *(const float4*)(pbl[j] + off);
            }
        }
        mma_chunk(AsH, AsL, BsH, BsL, acc, wm, wn, lane);
        __syncthreads();
    }
    int lq = lane>>2, lr = lane&3;
    #pragma unroll
    for(int mt=0; mt<2; mt++){
        #pragma unroll
        for(int nt=0; nt<8; nt++){
            int row = row0 + wm*32 + mt*16 + lq;
            int col = col0 + wn*64 + nt*8 + lr*2;
            float* c = acc[mt*8+nt];
            *(float2*)(Cm + (size_t)row*ldC + col)     = make_float2(c[0]*alpha, c[1]*alpha);
            *(float2*)(Cm + (size_t)(row+8)*ldC + col) = make_float2(c[2]*alpha, c[3]*alpha);
        }
    }
}

// ---------------- row softmax over T_, writes tf32-split P ----------------
__global__ void k_softmax(const float* __restrict__ S, float* __restrict__ PH,
                          float* __restrict__ PL){
    size_t row = blockIdx.x;
    const float* p = S + row*T_;
    int tid = threadIdx.x;
    float v[8];
    #pragma unroll
    for(int j=0;j<8;j++) v[j] = p[tid + j*256];
    float m = v[0];
    #pragma unroll
    for(int j=1;j<8;j++) m = fmaxf(m, v[j]);
    __shared__ float sm[40];
    for(int o=16;o;o>>=1) m = fmaxf(m, __shfl_xor_sync(0xffffffffu, m, o));
    if((tid&31)==0) sm[tid>>5] = m;
    __syncthreads();
    if(tid<32){
        float t = (tid<8)?sm[tid]:-3.0e38f;
        for(int o=4;o;o>>=1) t=fmaxf(t,__shfl_xor_sync(0xffffffffu,t,o));
        if(tid==0) sm[32]=t;
    }
    __syncthreads();
    m = sm[32];
    float s=0.f;
    #pragma unroll
    for(int j=0;j<8;j++){ v[j]=__expf(v[j]-m); s+=v[j]; }
    for(int o=16;o;o>>=1) s += __shfl_xor_sync(0xffffffffu, s, o);
    if((tid&31)==0) sm[tid>>5] = s;
    __syncthreads();
    if(tid<32){
        float t=(tid<8)?sm[tid]:0.f;
        for(int o=4;o;o>>=1) t+=__shfl_xor_sync(0xffffffffu,t,o);
        if(tid==0) sm[33]=t;
    }
    __syncthreads();
    float inv = 1.f/sm[33];
    size_t off = row*T_ + tid;
    #pragma unroll
    for(int j=0;j<8;j++){
        float pv = v[j]*inv;
        float h,l; tfsplit(pv, h, l);
        PH[off + j*256] = h;
        PL[off + j*256] = l;
    }
}

// ---------------- output proj + RevIN denorm ----------------
__global__ void k_final(const float* __restrict__ o, const float* __restrict__ w,
                        const float* __restrict__ ob, const float* __restrict__ rw,
                        const float* __restrict__ rb, float* __restrict__ out){
    int bt = blockIdx.x;
    int b  = bt >> 11;
    int e  = threadIdx.x;
    float x = o[(size_t)bt*E_ + e];
    float p0 = x*w[e], p1 = x*w[E_+e], p2 = x*w[2*E_+e];
    for(int s=16;s;s>>=1){
        p0 += __shfl_down_sync(0xffffffffu, p0, s);
        p1 += __shfl_down_sync(0xffffffffu, p1, s);
        p2 += __shfl_down_sync(0xffffffffu, p2, s);
    }
    __shared__ float sm[3][8];
    int wid=e>>5, lane=e&31;
    if(lane==0){ sm[0][wid]=p0; sm[1][wid]=p1; sm[2][wid]=p2; }
    __syncthreads();
    if(e < C_){
        float s=0.f;
        #pragma unroll
        for(int wdx=0;wdx<8;wdx++) s += sm[e][wdx];
        int c = e;
        float val = s + ob[c];
        val = (val - rb[c]) / rw[c];
        val = val * g_std[b*C_+c] + g_mean[b*C_+c];
        out[(size_t)bt*C_ + c] = val;
    }
}

// ---------------- host orchestration (graph-capturable) ----------------
template<int DIL>
static void launch_mid(const float* src, const float* wt, P3 bm, float* dst, int layer){
    size_t smem = (size_t)(BN_*(128 + 14*DIL)) * sizeof(float);
    cudaFuncSetAttribute(k_conv_mid<DIL>, cudaFuncAttributeMaxDynamicSharedMemorySize, (int)smem);
    k_conv_mid<DIL><<<dim3(T_/128, B_, 6), 128, smem>>>(src, wt, bm, dst, layer);
}

extern "C" void kernel_launch(void* const* d_in, const int* in_sizes, int n_in,
                              void* d_out, int out_size){
    const float* query = (const float*)d_in[0];
    const float* key   = (const float*)d_in[1];
    const float* out_w = (const float*)d_in[20];
    const float* out_b = (const float*)d_in[21];
    const float* rw    = (const float*)d_in[22];
    const float* rb    = (const float*)d_in[23];

    float *p_qn,*p_kn,*p_h0,*p_h1,*p_wt,*p_qh,*p_ql,*p_kh,*p_kl,*p_vth,*p_vtl;
    float *p_attn,*p_ph,*p_pl,*p_o;
    cudaGetSymbolAddress((void**)&p_qn,   g_qn);
    cudaGetSymbolAddress((void**)&p_kn,   g_kn);
    cudaGetSymbolAddress((void**)&p_h0,   g_h0);
    cudaGetSymbolAddress((void**)&p_h1,   g_h1);
    cudaGetSymbolAddress((void**)&p_wt,   g_wt);
    cudaGetSymbolAddress((void**)&p_qh,   g_qh);
    cudaGetSymbolAddress((void**)&p_ql,   g_ql);
    cudaGetSymbolAddress((void**)&p_kh,   g_kh);
    cudaGetSymbolAddress((void**)&p_kl,   g_kl);
    cudaGetSymbolAddress((void**)&p_vth,  g_vth);
    cudaGetSymbolAddress((void**)&p_vtl,  g_vtl);
    cudaGetSymbolAddress((void**)&p_attn, g_attn);
    cudaGetSymbolAddress((void**)&p_ph,   g_ph);
    cudaGetSymbolAddress((void**)&p_pl,   g_pl);
    cudaGetSymbolAddress((void**)&p_o,    g_o);

    P3 w_in  = {(const float*)d_in[2],  (const float*)d_in[8],  (const float*)d_in[14]};
    P3 b_in  = {(const float*)d_in[3],  (const float*)d_in[9],  (const float*)d_in[15]};
    P3 w_mid = {(const float*)d_in[4],  (const float*)d_in[10], (const float*)d_in[16]};
    P3 b_mid = {(const float*)d_in[5],  (const float*)d_in[11], (const float*)d_in[17]};
    P3 w_out = {(const float*)d_in[6],  (const float*)d_in[12], (const float*)d_in[18]};
    P3 b_out = {(const float*)d_in[7],  (const float*)d_in[13], (const float*)d_in[19]};

    k_stats<<<B_*C_, 256>>>(key);
    k_norm<<<(B_*C_*T_ + 255)/256, 256>>>(query, key, rw, rb);
    k_wtrans<<<dim3(D_, 3), 512>>>(w_mid, p_wt);

    k_conv_in<<<dim3(T_/256, B_, 3), 256>>>(p_qn, p_kn, w_in, b_in, p_h0);
    launch_mid<2 >(p_h0, p_wt, b_mid, p_h1, 0);
    launch_mid<4 >(p_h1, p_wt, b_mid, p_h0, 1);
    launch_mid<8 >(p_h0, p_wt, b_mid, p_h1, 2);
    launch_mid<16>(p_h1, p_wt, b_mid, p_h0, 3);
    launch_mid<32>(p_h0, p_wt, b_mid, p_h1, 4);
    k_conv_out<<<dim3(T_/32, B_, 3), 256>>>(p_h1, w_out, b_out,
                                            p_qh, p_ql, p_kh, p_kl, p_vth, p_vtl);

    // S = scale * Q K^T   (3xTF32 mma.sync, precomputed splits)
    k_mma_nt3<<<dim3(T_/128, T_/128, B_), 256>>>(
        p_qh, p_ql, p_kh, p_kl, p_attn, E_,
        (size_t)T_*E_, (size_t)T_*E_, (size_t)T_*T_, T_, 0.0625f);
    k_softmax<<<B_*T_, 256>>>(p_attn, p_ph, p_pl);
    // O = P V   (same NT kernel; V pre-transposed)
    k_mma_nt3<<<dim3(T_/128, E_/128, B_), 256>>>(
        p_ph, p_pl, p_vth, p_vtl, p_o, T_,
        (size_t)T_*T_, (size_t)E_*T_, (size_t)T_*E_, E_, 1.0f);
    k_final<<<B_*T_, 256>>>(p_o, out_w, out_b, rw, rb, (float*)d_out);
}

// round 7
// speedup vs baseline: 1.2203x; 1.2203x over previous
#include <cuda_runtime.h>
#include <math.h>
#include <stdint.h>

#define B_  8
#define T_  2048
#define C_  3
#define E_  256
#define K_  15
#define D_  5
#define BN_ 32
#define WSZ (BN_*BN_*K_)   // 15360 floats per mid layer

struct P3 { const float *q, *k, *v; };

__device__ __forceinline__ const float* pick(const P3& p, int net){
    return net==0 ? p.q : (net==1 ? p.k : p.v);
}

// ---------------- scratch (device globals; no allocs allowed) ----------------
static __device__ float g_mean[B_*C_];
static __device__ float g_std [B_*C_];
static __device__ float g_qn[B_*C_*T_];
static __device__ float g_kn[B_*C_*T_];
static __device__ float g_h0[3*B_*BN_*T_];
static __device__ float g_h1[3*B_*BN_*T_];
static __device__ float g_wt[3*D_*WSZ];           // mid weights transposed [net][layer][ci*15+k][cout]
static __device__ float g_qh[(size_t)B_*T_*E_];
static __device__ float g_ql[(size_t)B_*T_*E_];
static __device__ float g_kh[(size_t)B_*T_*E_];
static __device__ float g_kl[(size_t)B_*T_*E_];
static __device__ float g_vth[(size_t)B_*E_*T_];  // V transposed [B][E][T]
static __device__ float g_vtl[(size_t)B_*E_*T_];
static __device__ float g_attn[(size_t)B_*T_*T_]; // S raw (128 MiB)
static __device__ float g_ph[(size_t)B_*T_*T_];   // P split hi
static __device__ float g_pl[(size_t)B_*T_*T_];   // P split lo
static __device__ float g_o[(size_t)B_*T_*E_];

// ---------------- tf32 split ----------------
__device__ __forceinline__ void tfsplit(float x, float& h, float& l){
    unsigned hb; asm("cvt.rna.tf32.f32 %0, %1;" : "=r"(hb) : "f"(x));
    h = __uint_as_float(hb);
    float r = x - h;
    unsigned lb; asm("cvt.rna.tf32.f32 %0, %1;" : "=r"(lb) : "f"(r));
    l = __uint_as_float(lb);
}

// ---------------- RevIN stats over time of key_in ----------------
__global__ void k_stats(const float* __restrict__ key){
    int bc = blockIdx.x, b = bc / C_, c = bc % C_;
    int tid = threadIdx.x;
    float s = 0.f, ss = 0.f;
    for (int t = tid; t < T_; t += 256){
        float x = key[((size_t)b*T_ + t)*C_ + c];
        s += x; ss += x*x;
    }
    __shared__ float r1[256], r2[256];
    r1[tid]=s; r2[tid]=ss; __syncthreads();
    for(int o=128;o;o>>=1){ if(tid<o){ r1[tid]+=r1[tid+o]; r2[tid]+=r2[tid+o]; } __syncthreads(); }
    if(tid==0){
        float m = r1[0]/(float)T_;
        float v = r2[0]/(float)T_ - m*m;
        g_mean[bc]=m;
        g_std[bc]=sqrtf(v + 1e-5f);
    }
}

// ---------------- normalize + transpose to [B][C][T] ----------------
__global__ void k_norm(const float* __restrict__ q, const float* __restrict__ k,
                       const float* __restrict__ rw, const float* __restrict__ rb){
    int i = blockIdx.x*256 + threadIdx.x;
    if(i >= B_*C_*T_) return;
    int t = i % T_, c = (i / T_) % C_, b = i / (C_*T_);
    float m = g_mean[b*C_+c], inv = 1.f/g_std[b*C_+c];
    float w = rw[c], bb = rb[c];
    size_t src = ((size_t)b*T_ + t)*C_ + c;
    g_qn[i] = (q[src]-m)*inv*w + bb;
    g_kn[i] = (k[src]-m)*inv*w + bb;
}

// ---------------- transpose mid weights to [ci*15+k][cout] ----------------
__global__ void k_wtrans(P3 wm, float* __restrict__ wt){
    int layer = blockIdx.x, net = blockIdx.y;
    const float* src = pick(wm, net) + (size_t)layer*WSZ;
    float* dst = wt + ((size_t)(net*D_ + layer))*WSZ;
    for(int i=threadIdx.x; i<WSZ; i+=blockDim.x){
        int cout = i/480, rest = i - cout*480;
        dst[rest*BN_ + cout] = src[i];
    }
}

// ---------------- conv in (fused q/k/v): C_ -> BN_, K=15, dil=1, relu ------
__global__ void k_conv_in(const float* __restrict__ qn, const float* __restrict__ kn,
                          P3 w, P3 bias, float* __restrict__ dstbase){
    int net = blockIdx.z;
    const float* src = (net==0) ? qn : kn;
    const float* wp  = pick(w, net);
    const float* bp  = pick(bias, net);
    float* dst = dstbase + (size_t)net*B_*BN_*T_;

    __shared__ float ws[BN_*C_*K_];
    __shared__ float bs[BN_];
    __shared__ float xs[C_][256 + K_ - 1];
    int b = blockIdx.y, t0 = blockIdx.x*256, tid = threadIdx.x;
    for(int i=tid;i<BN_*C_*K_;i+=256) ws[i]=wp[i];
    if(tid<BN_) bs[tid]=bp[tid];
    const int W = 256 + K_ - 1;
    for(int i=tid;i<C_*W;i+=256){
        int ci=i/W, p=i%W, g=t0+p-7;
        xs[ci][p] = ((unsigned)g < T_) ? src[(b*C_+ci)*T_ + g] : 0.f;
    }
    __syncthreads();
    float acc[BN_];
    #pragma unroll
    for(int c=0;c<BN_;c++) acc[c]=bs[c];
    #pragma unroll
    for(int ci=0;ci<C_;ci++){
        #pragma unroll
        for(int k=0;k<K_;k++){
            float x = xs[ci][tid+k];
            #pragma unroll
            for(int c=0;c<BN_;c++) acc[c] += x * ws[(c*C_+ci)*K_+k];
        }
    }
    int t = t0 + tid;
    #pragma unroll
    for(int c=0;c<BN_;c++) dst[((size_t)b*BN_+c)*T_ + t] = fmaxf(acc[c], 0.f);
}

// ---------------- conv mid (fused q/k/v): BN_ -> BN_, K=15, dilated, relu --
// R2 design: transposed weights staged in smem ([ci*15+k][cout], coalesced
// float4 copy from pre-transposed g_wt), x tile in smem, acc[32] in regs.
template<int DIL>
__global__ void k_conv_mid(const float* __restrict__ srcbase,
                           const float* __restrict__ wt, P3 bm,
                           float* __restrict__ dstbase, int layer){
    constexpr int W = 128 + 14*DIL;
    constexpr int H = 7*DIL;
    extern __shared__ float sm[];
    float* ws = sm;           // WSZ floats, layout [ci*15+k][32]
    float* xs = sm + WSZ;     // 32 * W

    int net = blockIdx.z;
    const float* w    = wt + ((size_t)(net*D_ + layer))*WSZ;
    const float* bias = pick(bm, net) + layer*BN_;
    const float* src  = srcbase + (size_t)net*B_*BN_*T_;
    float* dst        = dstbase + (size_t)net*B_*BN_*T_;

    int b = blockIdx.y, t0 = blockIdx.x*128, tid = threadIdx.x;

    // coalesced float4 weight copy (already transposed)
    {
        const float4* s4 = (const float4*)w;
        float4* d4 = (float4*)ws;
        #pragma unroll
        for(int i=tid;i<WSZ/4;i+=128) d4[i]=s4[i];
    }
    for(int i=tid;i<BN_*W;i+=128){
        int ci = i/W, p = i - ci*W, g = t0 - H + p;
        xs[i] = ((unsigned)g < T_) ? src[(b*BN_+ci)*T_ + g] : 0.f;
    }
    __syncthreads();

    float acc[BN_];
    #pragma unroll
    for(int c=0;c<BN_;c++) acc[c]=__ldg(&bias[c]);

    for(int ci=0;ci<BN_;ci++){
        const float* xr = xs + ci*W + tid;
        #pragma unroll
        for(int k=0;k<K_;k++){
            float x = xr[k*DIL];
            const float4* wr = (const float4*)(ws + (ci*K_+k)*BN_);
            #pragma unroll
            for(int m=0;m<8;m++){
                float4 wv = wr[m];
                acc[4*m+0] += x*wv.x;
                acc[4*m+1] += x*wv.y;
                acc[4*m+2] += x*wv.z;
                acc[4*m+3] += x*wv.w;
            }
        }
    }
    int t = t0 + tid;
    #pragma unroll
    for(int c=0;c<BN_;c++) dst[((size_t)b*BN_+c)*T_ + t] = fmaxf(acc[c], 0.f);
}

// ------- conv out (fused, 1x1): BN_ -> E_, writes tf32-split Q/K/Vt -------
__global__ void k_conv_out(const float* __restrict__ srcbase, P3 w, P3 bias,
                           float* __restrict__ qh, float* __restrict__ ql,
                           float* __restrict__ kh, float* __restrict__ kl,
                           float* __restrict__ vth, float* __restrict__ vtl){
    int net = blockIdx.z;
    const float* src = srcbase + (size_t)net*B_*BN_*T_;
    const float* wp  = pick(w, net);
    const float* bp  = pick(bias, net);

    __shared__ float xs[BN_][32];
    int b = blockIdx.y, t0 = blockIdx.x*32, e = threadIdx.x;
    for(int i=e;i<BN_*32;i+=256){
        int ci=i>>5, tl=i&31;
        xs[ci][tl] = src[((size_t)b*BN_+ci)*T_ + t0 + tl];
    }
    __syncthreads();
    float acc[32];
    float bb = bp[e];
    #pragma unroll
    for(int t=0;t<32;t++) acc[t]=bb;
    #pragma unroll 4
    for(int ci=0;ci<BN_;ci++){
        float wv = __ldg(&wp[e*BN_+ci]);
        #pragma unroll
        for(int t=0;t<32;t++) acc[t] += xs[ci][t]*wv;
    }
    if(net < 2){
        float* H = net ? kh : qh;
        float* L = net ? kl : ql;
        #pragma unroll
        for(int t=0;t<32;t++){
            float h,l; tfsplit(acc[t], h, l);
            size_t o = ((size_t)b*T_ + t0+t)*E_ + e;
            H[o]=h; L[o]=l;
        }
    } else {
        size_t o = ((size_t)b*E_ + e)*T_ + t0;
        #pragma unroll
        for(int t=0;t<32;t++){
            float h,l; tfsplit(acc[t], h, l);
            vth[o+t]=h; vtl[o+t]=l;
        }
    }
}

// =================== 3xTF32 mma.sync GEMM, NT form, precomputed splits =====
__device__ __forceinline__ void mma8(float* c, const unsigned* a, unsigned b0, unsigned b1){
    asm volatile(
        "mma.sync.aligned.m16n8k8.row.col.f32.tf32.tf32.f32 "
        "{%0,%1,%2,%3},{%4,%5,%6,%7},{%8,%9},{%0,%1,%2,%3};"
        : "+f"(c[0]), "+f"(c[1]), "+f"(c[2]), "+f"(c[3])
        : "r"(a[0]), "r"(a[1]), "r"(a[2]), "r"(a[3]), "r"(b0), "r"(b1));
}

#define SKM 136   // padded smem leading dim

__device__ __forceinline__ void mma_chunk(
    const unsigned (*AsH)[SKM], const unsigned (*AsL)[SKM],
    const unsigned (*BsH)[SKM], const unsigned (*BsL)[SKM],
    float acc[16][4], int wm, int wn, int lane)
{
    int lq = lane >> 2, lr = lane & 3;
    #pragma unroll
    for(int ks=0; ks<2; ks++){
        int kb = ks*8 + lr;
        unsigned aH[2][4], aL[2][4];
        #pragma unroll
        for(int mt=0; mt<2; mt++){
            int rm = wm*32 + mt*16 + lq;
            aH[mt][0]=AsH[kb  ][rm];  aH[mt][1]=AsH[kb  ][rm+8];
            aH[mt][2]=AsH[kb+4][rm];  aH[mt][3]=AsH[kb+4][rm+8];
            aL[mt][0]=AsL[kb  ][rm];  aL[mt][1]=AsL[kb  ][rm+8];
            aL[mt][2]=AsL[kb+4][rm];  aL[mt][3]=AsL[kb+4][rm+8];
        }
        #pragma unroll
        for(int nt=0; nt<8; nt++){
            int cn = wn*64 + nt*8 + lq;
            unsigned bH0=BsH[kb][cn], bH1=BsH[kb+4][cn];
            unsigned bL0=BsL[kb][cn], bL1=BsL[kb+4][cn];
            #pragma unroll
            for(int mt=0; mt<2; mt++){
                mma8(acc[mt*8+nt], aH[mt], bH0, bH1);
                mma8(acc[mt*8+nt], aH[mt], bL0, bL1);
                mma8(acc[mt*8+nt], aL[mt], bH0, bH1);
            }
        }
    }
}

// C[M,N] = alpha * A[M,K] * B[N,K]^T  with A/B pre-split into hi/lo arrays
__global__ void __launch_bounds__(256)
k_mma_nt3(const float* __restrict__ Ah, const float* __restrict__ Al,
          const float* __restrict__ Bh, const float* __restrict__ Bl,
          float* __restrict__ Cm, int Kdim,
          size_t sA, size_t sB, size_t sC, int ldC, float alpha){
    __shared__ unsigned AsH[16][SKM], AsL[16][SKM], BsH[16][SKM], BsL[16][SKM];
    int bz = blockIdx.z;
    Ah += bz*sA; Al += bz*sA;
    Bh += bz*sB; Bl += bz*sB;
    Cm += bz*sC;
    int tid = threadIdx.x, lane = tid & 31, wid = tid >> 5;
    int wm = wid & 3, wn = wid >> 2;
    int row0 = blockIdx.x*128, col0 = blockIdx.y*128;

    float acc[16][4];
    #pragma unroll
    for(int i=0;i<16;i++){ acc[i][0]=acc[i][1]=acc[i][2]=acc[i][3]=0.f; }

    int r[2], c4[2];
    const float *pah[2], *pal[2], *pbh[2], *pbl[2];
    #pragma unroll
    for(int j=0;j<2;j++){
        int idx = tid + j*256;
        r[j] = idx>>2; c4[j] = (idx&3)<<2;
        size_t oa = (size_t)(row0+r[j])*Kdim + c4[j];
        size_t ob = (size_t)(col0+r[j])*Kdim + c4[j];
        pah[j] = Ah + oa; pal[j] = Al + oa;
        pbh[j] = Bh + ob; pbl[j] = Bl + ob;
    }
    float4 vah[2], val_[2], vbh[2], vbl[2];
    #pragma unroll
    for(int j=0;j<2;j++){
        vah[j] = *(const float4*)pah[j];  val_[j] = *(const float4*)pal[j];
        vbh[j] = *(const float4*)pbh[j];  vbl[j] = *(const float4*)pbl[j];
    }

    const int NCH = Kdim >> 4;
    for(int ch=0; ch<NCH; ch++){
        #pragma unroll
        for(int j=0;j<2;j++){
            int cc = c4[j], rr = r[j];
            AsH[cc+0][rr]=__float_as_uint(vah[j].x); AsH[cc+1][rr]=__float_as_uint(vah[j].y);
            AsH[cc+2][rr]=__float_as_uint(vah[j].z); AsH[cc+3][rr]=__float_as_uint(vah[j].w);
            AsL[cc+0][rr]=__float_as_uint(val_[j].x); AsL[cc+1][rr]=__float_as_uint(val_[j].y);
            AsL[cc+2][rr]=__float_as_uint(val_[j].z); AsL[cc+3][rr]=__float_as_uint(val_[j].w);
            BsH[cc+0][rr]=__float_as_uint(vbh[j].x); BsH[cc+1][rr]=__float_as_uint(vbh[j].y);
            BsH[cc+2][rr]=__float_as_uint(vbh[j].z); BsH[cc+3][rr]=__float_as_uint(vbh[j].w);
            BsL[cc+0][rr]=__float_as_uint(vbl[j].x); BsL[cc+1][rr]=__float_as_uint(vbl[j].y);
            BsL[cc+2][rr]=__float_as_uint(vbl[j].z); BsL[cc+3][rr]=__float_as_uint(vbl[j].w);
        }
        __syncthreads();
        if(ch+1 < NCH){
            int off = (ch+1)*16;
            #pragma unroll
            for(int j=0;j<2;j++){
                vah[j] = *(const float4*)(pah[j] + off);
                val_[j] = *(const float4*)(pal[j] + off);
                vbh[j] = *(const float4*)(pbh[j] + off);
                vbl[j] = *(const float4*)(pbl[j] + off);
            }
        }
        mma_chunk(AsH, AsL, BsH, BsL, acc, wm, wn, lane);
        __syncthreads();
    }
    int lq = lane>>2, lr = lane&3;
    #pragma unroll
    for(int mt=0; mt<2; mt++){
        #pragma unroll
        for(int nt=0; nt<8; nt++){
            int row = row0 + wm*32 + mt*16 + lq;
            int col = col0 + wn*64 + nt*8 + lr*2;
            float* c = acc[mt*8+nt];
            *(float2*)(Cm + (size_t)row*ldC + col)     = make_float2(c[0]*alpha, c[1]*alpha);
            *(float2*)(Cm + (size_t)(row+8)*ldC + col) = make_float2(c[2]*alpha, c[3]*alpha);
        }
    }
}

// ---------------- row softmax over T_, writes tf32-split P ----------------
__global__ void k_softmax(const float* __restrict__ S, float* __restrict__ PH,
                          float* __restrict__ PL){
    size_t row = blockIdx.x;
    const float* p = S + row*T_;
    int tid = threadIdx.x;
    float v[8];
    #pragma unroll
    for(int j=0;j<8;j++) v[j] = p[tid + j*256];
    float m = v[0];
    #pragma unroll
    for(int j=1;j<8;j++) m = fmaxf(m, v[j]);
    __shared__ float sm[40];
    for(int o=16;o;o>>=1) m = fmaxf(m, __shfl_xor_sync(0xffffffffu, m, o));
    if((tid&31)==0) sm[tid>>5] = m;
    __syncthreads();
    if(tid<32){
        float t = (tid<8)?sm[tid]:-3.0e38f;
        for(int o=4;o;o>>=1) t=fmaxf(t,__shfl_xor_sync(0xffffffffu,t,o));
        if(tid==0) sm[32]=t;
    }
    __syncthreads();
    m = sm[32];
    float s=0.f;
    #pragma unroll
    for(int j=0;j<8;j++){ v[j]=__expf(v[j]-m); s+=v[j]; }
    for(int o=16;o;o>>=1) s += __shfl_xor_sync(0xffffffffu, s, o);
    if((tid&31)==0) sm[tid>>5] = s;
    __syncthreads();
    if(tid<32){
        float t=(tid<8)?sm[tid]:0.f;
        for(int o=4;o;o>>=1) t+=__shfl_xor_sync(0xffffffffu,t,o);
        if(tid==0) sm[33]=t;
    }
    __syncthreads();
    float inv = 1.f/sm[33];
    size_t off = row*T_ + tid;
    #pragma unroll
    for(int j=0;j<8;j++){
        float pv = v[j]*inv;
        float h,l; tfsplit(pv, h, l);
        PH[off + j*256] = h;
        PL[off + j*256] = l;
    }
}

// ---------------- output proj + RevIN denorm ----------------
__global__ void k_final(const float* __restrict__ o, const float* __restrict__ w,
                        const float* __restrict__ ob, const float* __restrict__ rw,
                        const float* __restrict__ rb, float* __restrict__ out){
    int bt = blockIdx.x;
    int b  = bt >> 11;
    int e  = threadIdx.x;
    float x = o[(size_t)bt*E_ + e];
    float p0 = x*w[e], p1 = x*w[E_+e], p2 = x*w[2*E_+e];
    for(int s=16;s;s>>=1){
        p0 += __shfl_down_sync(0xffffffffu, p0, s);
        p1 += __shfl_down_sync(0xffffffffu, p1, s);
        p2 += __shfl_down_sync(0xffffffffu, p2, s);
    }
    __shared__ float sm[3][8];
    int wid=e>>5, lane=e&31;
    if(lane==0){ sm[0][wid]=p0; sm[1][wid]=p1; sm[2][wid]=p2; }
    __syncthreads();
    if(e < C_){
        float s=0.f;
        #pragma unroll
        for(int wdx=0;wdx<8;wdx++) s += sm[e][wdx];
        int c = e;
        float val = s + ob[c];
        val = (val - rb[c]) / rw[c];
        val = val * g_std[b*C_+c] + g_mean[b*C_+c];
        out[(size_t)bt*C_ + c] = val;
    }
}

// ---------------- host orchestration (graph-capturable) ----------------
template<int DIL>
static void launch_mid(const float* src, const float* wt, P3 bm, float* dst, int layer){
    size_t smem = (size_t)(WSZ + BN_*(128 + 14*DIL)) * sizeof(float);
    cudaFuncSetAttribute(k_conv_mid<DIL>, cudaFuncAttributeMaxDynamicSharedMemorySize, (int)smem);
    k_conv_mid<DIL><<<dim3(T_/128, B_, 3), 128, smem>>>(src, wt, bm, dst, layer);
}

extern "C" void kernel_launch(void* const* d_in, const int* in_sizes, int n_in,
                              void* d_out, int out_size){
    const float* query = (const float*)d_in[0];
    const float* key   = (const float*)d_in[1];
    const float* out_w = (const float*)d_in[20];
    const float* out_b = (const float*)d_in[21];
    const float* rw    = (const float*)d_in[22];
    const float* rb    = (const float*)d_in[23];

    float *p_qn,*p_kn,*p_h0,*p_h1,*p_wt,*p_qh,*p_ql,*p_kh,*p_kl,*p_vth,*p_vtl;
    float *p_attn,*p_ph,*p_pl,*p_o;
    cudaGetSymbolAddress((void**)&p_qn,   g_qn);
    cudaGetSymbolAddress((void**)&p_kn,   g_kn);
    cudaGetSymbolAddress((void**)&p_h0,   g_h0);
    cudaGetSymbolAddress((void**)&p_h1,   g_h1);
    cudaGetSymbolAddress((void**)&p_wt,   g_wt);
    cudaGetSymbolAddress((void**)&p_qh,   g_qh);
    cudaGetSymbolAddress((void**)&p_ql,   g_ql);
    cudaGetSymbolAddress((void**)&p_kh,   g_kh);
    cudaGetSymbolAddress((void**)&p_kl,   g_kl);
    cudaGetSymbolAddress((void**)&p_vth,  g_vth);
    cudaGetSymbolAddress((void**)&p_vtl,  g_vtl);
    cudaGetSymbolAddress((void**)&p_attn, g_attn);
    cudaGetSymbolAddress((void**)&p_ph,   g_ph);
    cudaGetSymbolAddress((void**)&p_pl,   g_pl);
    cudaGetSymbolAddress((void**)&p_o,    g_o);

    P3 w_in  = {(const float*)d_in[2],  (const float*)d_in[8],  (const float*)d_in[14]};
    P3 b_in  = {(const float*)d_in[3],  (const float*)d_in[9],  (const float*)d_in[15]};
    P3 w_mid = {(const float*)d_in[4],  (const float*)d_in[10], (const float*)d_in[16]};
    P3 b_mid = {(const float*)d_in[5],  (const float*)d_in[11], (const float*)d_in[17]};
    P3 w_out = {(const float*)d_in[6],  (const float*)d_in[12], (const float*)d_in[18]};
    P3 b_out = {(const float*)d_in[7],  (const float*)d_in[13], (const float*)d_in[19]};

    k_stats<<<B_*C_, 256>>>(key);
    k_norm<<<(B_*C_*T_ + 255)/256, 256>>>(query, key, rw, rb);
    k_wtrans<<<dim3(D_, 3), 512>>>(w_mid, p_wt);

    k_conv_in<<<dim3(T_/256, B_, 3), 256>>>(p_qn, p_kn, w_in, b_in, p_h0);
    launch_mid<2 >(p_h0, p_wt, b_mid, p_h1, 0);
    launch_mid<4 >(p_h1, p_wt, b_mid, p_h0, 1);
    launch_mid<8 >(p_h0, p_wt, b_mid, p_h1, 2);
    launch_mid<16>(p_h1, p_wt, b_mid, p_h0, 3);
    launch_mid<32>(p_h0, p_wt, b_mid, p_h1, 4);
    k_conv_out<<<dim3(T_/32, B_, 3), 256>>>(p_h1, w_out, b_out,
                                            p_qh, p_ql, p_kh, p_kl, p_vth, p_vtl);

    // S = scale * Q K^T   (3xTF32 mma.sync, precomputed splits)
    k_mma_nt3<<<dim3(T_/128, T_/128, B_), 256>>>(
        p_qh, p_ql, p_kh, p_kl, p_attn, E_,
        (size_t)T_*E_, (size_t)T_*E_, (size_t)T_*T_, T_, 0.0625f);
    k_softmax<<<B_*T_, 256>>>(p_attn, p_ph, p_pl);
    // O = P V   (same NT kernel; V pre-transposed)
    k_mma_nt3<<<dim3(T_/128, E_/128, B_), 256>>>(
        p_ph, p_pl, p_vth, p_vtl, p_o, T_,
        (size_t)T_*T_, (size_t)E_*T_, (size_t)T_*E_, E_, 1.0f);
    k_final<<<B_*T_, 256>>>(p_o, out_w, out_b, rw, rb, (float*)d_out);
}

// round 10
// speedup vs baseline: 1.7017x; 1.3945x over previous
#include <cuda_runtime.h>
#include <cuda_bf16.h>
#include <math.h>
#include <stdint.h>

#define B_  8
#define T_  2048
#define C_  3
#define E_  256
#define K_  15
#define D_  5
#define BN_ 32
#define WSZ (BN_*BN_*K_)   // 15360 floats per mid layer

struct P3 { const float *q, *k, *v; };

__device__ __forceinline__ const float* pick(const P3& p, int net){
    return net==0 ? p.q : (net==1 ? p.k : p.v);
}

typedef __nv_bfloat16 bf16;

// ---------------- scratch (device globals; no allocs allowed) ----------------
static __device__ float g_mean[B_*C_];
static __device__ float g_std [B_*C_];
static __device__ float g_qn[B_*C_*T_];
static __device__ float g_kn[B_*C_*T_];
static __device__ float g_h0[3*B_*BN_*T_];
static __device__ float g_h1[3*B_*BN_*T_];
static __device__ float g_wt[3*D_*WSZ];           // mid weights transposed
static __device__ __align__(16) bf16 g_qh[(size_t)B_*T_*E_];
static __device__ __align__(16) bf16 g_ql[(size_t)B_*T_*E_];
static __device__ __align__(16) bf16 g_kh[(size_t)B_*T_*E_];
static __device__ __align__(16) bf16 g_kl[(size_t)B_*T_*E_];
static __device__ __align__(16) bf16 g_vth[(size_t)B_*E_*T_];  // V^T [B][E][T]
static __device__ __align__(16) bf16 g_vtl[(size_t)B_*E_*T_];
static __device__ float g_attn[(size_t)B_*T_*T_];              // S raw (128 MiB)
static __device__ __align__(16) bf16 g_ph[(size_t)B_*T_*T_];   // P split hi (64 MiB)
static __device__ __align__(16) bf16 g_pl[(size_t)B_*T_*T_];   // P split lo
static __device__ float g_o[(size_t)B_*T_*E_];

// ---------------- bf16 split ----------------
__device__ __forceinline__ void bfsplit(float x, bf16& h, bf16& l){
    h = __float2bfloat16_rn(x);
    l = __float2bfloat16_rn(x - __bfloat162float(h));
}

// ---------------- RevIN stats over time of key_in ----------------
__global__ void k_stats(const float* __restrict__ key){
    int bc = blockIdx.x, b = bc / C_, c = bc % C_;
    int tid = threadIdx.x;
    float s = 0.f, ss = 0.f;
    for (int t = tid; t < T_; t += 256){
        float x = key[((size_t)b*T_ + t)*C_ + c];
        s += x; ss += x*x;
    }
    __shared__ float r1[256], r2[256];
    r1[tid]=s; r2[tid]=ss; __syncthreads();
    for(int o=128;o;o>>=1){ if(tid<o){ r1[tid]+=r1[tid+o]; r2[tid]+=r2[tid+o]; } __syncthreads(); }
    if(tid==0){
        float m = r1[0]/(float)T_;
        float v = r2[0]/(float)T_ - m*m;
        g_mean[bc]=m;
        g_std[bc]=sqrtf(v + 1e-5f);
    }
}

// ---------------- normalize + transpose to [B][C][T] ----------------
__global__ void k_norm(const float* __restrict__ q, const float* __restrict__ k,
                       const float* __restrict__ rw, const float* __restrict__ rb){
    int i = blockIdx.x*256 + threadIdx.x;
    if(i >= B_*C_*T_) return;
    int t = i % T_, c = (i / T_) % C_, b = i / (C_*T_);
    float m = g_mean[b*C_+c], inv = 1.f/g_std[b*C_+c];
    float w = rw[c], bb = rb[c];
    size_t src = ((size_t)b*T_ + t)*C_ + c;
    g_qn[i] = (q[src]-m)*inv*w + bb;
    g_kn[i] = (k[src]-m)*inv*w + bb;
}

// ---------------- transpose mid weights to [ci*15+k][cout] ----------------
__global__ void k_wtrans(P3 wm, float* __restrict__ wt){
    int layer = blockIdx.x, net = blockIdx.y;
    const float* src = pick(wm, net) + (size_t)layer*WSZ;
    float* dst = wt + ((size_t)(net*D_ + layer))*WSZ;
    for(int i=threadIdx.x; i<WSZ; i+=blockDim.x){
        int cout = i/480, rest = i - cout*480;
        dst[rest*BN_ + cout] = src[i];
    }
}

// ---------------- conv in (fused q/k/v): C_ -> BN_, K=15, dil=1, relu ------
__global__ void k_conv_in(const float* __restrict__ qn, const float* __restrict__ kn,
                          P3 w, P3 bias, float* __restrict__ dstbase){
    int net = blockIdx.z;
    const float* src = (net==0) ? qn : kn;
    const float* wp  = pick(w, net);
    const float* bp  = pick(bias, net);
    float* dst = dstbase + (size_t)net*B_*BN_*T_;

    __shared__ float ws[BN_*C_*K_];
    __shared__ float bs[BN_];
    __shared__ float xs[C_][256 + K_ - 1];
    int b = blockIdx.y, t0 = blockIdx.x*256, tid = threadIdx.x;
    for(int i=tid;i<BN_*C_*K_;i+=256) ws[i]=wp[i];
    if(tid<BN_) bs[tid]=bp[tid];
    const int W = 256 + K_ - 1;
    for(int i=tid;i<C_*W;i+=256){
        int ci=i/W, p=i%W, g=t0+p-7;
        xs[ci][p] = ((unsigned)g < T_) ? src[(b*C_+ci)*T_ + g] : 0.f;
    }
    __syncthreads();
    float acc[BN_];
    #pragma unroll
    for(int c=0;c<BN_;c++) acc[c]=bs[c];
    #pragma unroll
    for(int ci=0;ci<C_;ci++){
        #pragma unroll
        for(int k=0;k<K_;k++){
            float x = xs[ci][tid+k];
            #pragma unroll
            for(int c=0;c<BN_;c++) acc[c] += x * ws[(c*C_+ci)*K_+k];
        }
    }
    int t = t0 + tid;
    #pragma unroll
    for(int c=0;c<BN_;c++) dst[((size_t)b*BN_+c)*T_ + t] = fmaxf(acc[c], 0.f);
}

// ---------------- conv mid (fused q/k/v): BN_ -> BN_, dilated, relu --------
template<int DIL>
__global__ void k_conv_mid(const float* __restrict__ srcbase,
                           const float* __restrict__ wt, P3 bm,
                           float* __restrict__ dstbase, int layer){
    constexpr int W = 128 + 14*DIL;
    constexpr int H = 7*DIL;
    extern __shared__ float sm[];
    float* ws = sm;           // WSZ floats, layout [ci*15+k][32]
    float* xs = sm + WSZ;     // 32 * W

    int net = blockIdx.z;
    const float* w    = wt + ((size_t)(net*D_ + layer))*WSZ;
    const float* bias = pick(bm, net) + layer*BN_;
    const float* src  = srcbase + (size_t)net*B_*BN_*T_;
    float* dst        = dstbase + (size_t)net*B_*BN_*T_;

    int b = blockIdx.y, t0 = blockIdx.x*128, tid = threadIdx.x;

    {
        const float4* s4 = (const float4*)w;
        float4* d4 = (float4*)ws;
        #pragma unroll
        for(int i=tid;i<WSZ/4;i+=128) d4[i]=s4[i];
    }
    for(int i=tid;i<BN_*W;i+=128){
        int ci = i/W, p = i - ci*W, g = t0 - H + p;
        xs[i] = ((unsigned)g < T_) ? src[(b*BN_+ci)*T_ + g] : 0.f;
    }
    __syncthreads();

    float acc[BN_];
    #pragma unroll
    for(int c=0;c<BN_;c++) acc[c]=__ldg(&bias[c]);

    for(int ci=0;ci<BN_;ci++){
        const float* xr = xs + ci*W + tid;
        #pragma unroll
        for(int k=0;k<K_;k++){
            float x = xr[k*DIL];
            const float4* wr = (const float4*)(ws + (ci*K_+k)*BN_);
            #pragma unroll
            for(int m=0;m<8;m++){
                float4 wv = wr[m];
                acc[4*m+0] += x*wv.x;
                acc[4*m+1] += x*wv.y;
                acc[4*m+2] += x*wv.z;
                acc[4*m+3] += x*wv.w;
            }
        }
    }
    int t = t0 + tid;
    #pragma unroll
    for(int c=0;c<BN_;c++) dst[((size_t)b*BN_+c)*T_ + t] = fmaxf(acc[c], 0.f);
}

// ------- conv out (fused, 1x1): BN_ -> E_, writes bf16-split Q/K/Vt -------
__global__ void k_conv_out(const float* __restrict__ srcbase, P3 w, P3 bias,
                           bf16* __restrict__ qh, bf16* __restrict__ ql,
                           bf16* __restrict__ kh, bf16* __restrict__ kl,
                           bf16* __restrict__ vth, bf16* __restrict__ vtl){
    int net = blockIdx.z;
    const float* src = srcbase + (size_t)net*B_*BN_*T_;
    const float* wp  = pick(w, net);
    const float* bp  = pick(bias, net);

    __shared__ float xs[BN_][32];
    int b = blockIdx.y, t0 = blockIdx.x*32, e = threadIdx.x;
    for(int i=e;i<BN_*32;i+=256){
        int ci=i>>5, tl=i&31;
        xs[ci][tl] = src[((size_t)b*BN_+ci)*T_ + t0 + tl];
    }
    __syncthreads();
    float acc[32];
    float bb = bp[e];
    #pragma unroll
    for(int t=0;t<32;t++) acc[t]=bb;
    #pragma unroll 4
    for(int ci=0;ci<BN_;ci++){
        float wv = __ldg(&wp[e*BN_+ci]);
        #pragma unroll
        for(int t=0;t<32;t++) acc[t] += xs[ci][t]*wv;
    }
    if(net < 2){
        bf16* H = net ? kh : qh;
        bf16* L = net ? kl : ql;
        #pragma unroll
        for(int t=0;t<32;t++){
            bf16 h,l; bfsplit(acc[t], h, l);
            size_t o = ((size_t)b*T_ + t0+t)*E_ + e;
            H[o]=h; L[o]=l;
        }
    } else {
        size_t o = ((size_t)b*E_ + e)*T_ + t0;
        #pragma unroll
        for(int t=0;t<32;t++){
            bf16 h,l; bfsplit(acc[t], h, l);
            vth[o+t]=h; vtl[o+t]=l;
        }
    }
}

// =========== 3xBF16 mma.sync m16n8k16 GEMM, NT form, bf16-split inputs =====
__device__ __forceinline__ void mma16(float* c, const unsigned* a, unsigned b0, unsigned b1){
    asm volatile(
        "mma.sync.aligned.m16n8k16.row.col.f32.bf16.bf16.f32 "
        "{%0,%1,%2,%3},{%4,%5,%6,%7},{%8,%9},{%0,%1,%2,%3};"
        : "+f"(c[0]), "+f"(c[1]), "+f"(c[2]), "+f"(c[3])
        : "r"(a[0]), "r"(a[1]), "r"(a[2]), "r"(a[3]), "r"(b0), "r"(b1));
}

#define SKM 136   // padded leading dim (words)

__device__ __forceinline__ void mma_chunk_bf(
    const unsigned (*AsH)[SKM], const unsigned (*AsL)[SKM],
    const unsigned (*BsH)[SKM], const unsigned (*BsL)[SKM],
    float acc[16][4], int wm, int wn, int lane)
{
    int lq = lane >> 2, lr = lane & 3;
    unsigned aH[2][4], aL[2][4];
    #pragma unroll
    for(int mt=0; mt<2; mt++){
        int rm = wm*32 + mt*16 + lq;
        aH[mt][0]=AsH[lr  ][rm];  aH[mt][1]=AsH[lr  ][rm+8];
        aH[mt][2]=AsH[lr+4][rm];  aH[mt][3]=AsH[lr+4][rm+8];
        aL[mt][0]=AsL[lr  ][rm];  aL[mt][1]=AsL[lr  ][rm+8];
        aL[mt][2]=AsL[lr+4][rm];  aL[mt][3]=AsL[lr+4][rm+8];
    }
    #pragma unroll
    for(int nt=0; nt<8; nt++){
        int cn = wn*64 + nt*8 + lq;
        unsigned bH0=BsH[lr][cn], bH1=BsH[lr+4][cn];
        unsigned bL0=BsL[lr][cn], bL1=BsL[lr+4][cn];
        #pragma unroll
        for(int mt=0; mt<2; mt++){
            mma16(acc[mt*8+nt], aH[mt], bH0, bH1);
            mma16(acc[mt*8+nt], aH[mt], bL0, bL1);
            mma16(acc[mt*8+nt], aL[mt], bH0, bH1);
        }
    }
}

// C[M,N] = alpha * A[M,K] * B[N,K]^T, A/B as bf16 hi/lo arrays (K contiguous)
__global__ void __launch_bounds__(256)
k_mma_bf(const bf16* __restrict__ Ah, const bf16* __restrict__ Al,
         const bf16* __restrict__ Bh, const bf16* __restrict__ Bl,
         float* __restrict__ Cm, int Kdim,
         size_t sA, size_t sB, size_t sC, int ldC, float alpha){
    __shared__ unsigned AsH[8][SKM], AsL[8][SKM], BsH[8][SKM], BsL[8][SKM];
    int bz = blockIdx.z;
    Ah += bz*sA; Al += bz*sA;
    Bh += bz*sB; Bl += bz*sB;
    Cm += bz*sC;
    int tid = threadIdx.x, lane = tid & 31, wid = tid >> 5;
    int wm = wid & 3, wn = wid >> 2;
    int row0 = blockIdx.x*128, col0 = blockIdx.y*128;

    float acc[16][4];
    #pragma unroll
    for(int i=0;i<16;i++){ acc[i][0]=acc[i][1]=acc[i][2]=acc[i][3]=0.f; }

    // loader mapping: r = tid>>1 (row), w4 = (tid&1)*4 (word offset within chunk)
    int r = tid >> 1, w4 = (tid & 1) * 4;
    const unsigned* wAh = (const unsigned*)(Ah + (size_t)(row0+r)*Kdim);
    const unsigned* wAl = (const unsigned*)(Al + (size_t)(row0+r)*Kdim);
    const unsigned* wBh = (const unsigned*)(Bh + (size_t)(col0+r)*Kdim);
    const unsigned* wBl = (const unsigned*)(Bl + (size_t)(col0+r)*Kdim);

    uint4 vah, val_, vbh, vbl;
    vah = *(const uint4*)(wAh + w4);
    val_ = *(const uint4*)(wAl + w4);
    vbh = *(const uint4*)(wBh + w4);
    vbl = *(const uint4*)(wBl + w4);

    const int NCH = Kdim >> 4;     // 16 k per chunk = 8 words
    for(int ch=0; ch<NCH; ch++){
        AsH[w4+0][r]=vah.x; AsH[w4+1][r]=vah.y; AsH[w4+2][r]=vah.z; AsH[w4+3][r]=vah.w;
        AsL[w4+0][r]=val_.x; AsL[w4+1][r]=val_.y; AsL[w4+2][r]=val_.z; AsL[w4+3][r]=val_.w;
        BsH[w4+0][r]=vbh.x; BsH[w4+1][r]=vbh.y; BsH[w4+2][r]=vbh.z; BsH[w4+3][r]=vbh.w;
        BsL[w4+0][r]=vbl.x; BsL[w4+1][r]=vbl.y; BsL[w4+2][r]=vbl.z; BsL[w4+3][r]=vbl.w;
        __syncthreads();
        if(ch+1 < NCH){
            int wo = (ch+1)*8 + w4;
            vah = *(const uint4*)(wAh + wo);
            val_ = *(const uint4*)(wAl + wo);
            vbh = *(const uint4*)(wBh + wo);
            vbl = *(const uint4*)(wBl + wo);
        }
        mma_chunk_bf(AsH, AsL, BsH, BsL, acc, wm, wn, lane);
        __syncthreads();
    }
    int lq = lane>>2, lr = lane&3;
    #pragma unroll
    for(int mt=0; mt<2; mt++){
        #pragma unroll
        for(int nt=0; nt<8; nt++){
            int row = row0 + wm*32 + mt*16 + lq;
            int col = col0 + wn*64 + nt*8 + lr*2;
            float* c = acc[mt*8+nt];
            *(float2*)(Cm + (size_t)row*ldC + col)     = make_float2(c[0]*alpha, c[1]*alpha);
            *(float2*)(Cm + (size_t)(row+8)*ldC + col) = make_float2(c[2]*alpha, c[3]*alpha);
        }
    }
}

// ---------------- row softmax over T_, writes bf16-split P ----------------
__global__ void k_softmax(const float* __restrict__ S, bf16* __restrict__ PH,
                          bf16* __restrict__ PL){
    size_t row = blockIdx.x;
    const float* p = S + row*T_;
    int tid = threadIdx.x;
    float v[8];
    #pragma unroll
    for(int j=0;j<8;j++) v[j] = p[tid + j*256];
    float m = v[0];
    #pragma unroll
    for(int j=1;j<8;j++) m = fmaxf(m, v[j]);
    __shared__ float sm[40];
    for(int o=16;o;o>>=1) m = fmaxf(m, __shfl_xor_sync(0xffffffffu, m, o));
    if((tid&31)==0) sm[tid>>5] = m;
    __syncthreads();
    if(tid<32){
        float t = (tid<8)?sm[tid]:-3.0e38f;
        for(int o=4;o;o>>=1) t=fmaxf(t,__shfl_xor_sync(0xffffffffu,t,o));
        if(tid==0) sm[32]=t;
    }
    __syncthreads();
    m = sm[32];
    float s=0.f;
    #pragma unroll
    for(int j=0;j<8;j++){ v[j]=__expf(v[j]-m); s+=v[j]; }
    for(int o=16;o;o>>=1) s += __shfl_xor_sync(0xffffffffu, s, o);
    if((tid&31)==0) sm[tid>>5] = s;
    __syncthreads();
    if(tid<32){
        float t=(tid<8)?sm[tid]:0.f;
        for(int o=4;o;o>>=1) t+=__shfl_xor_sync(0xffffffffu,t,o);
        if(tid==0) sm[33]=t;
    }
    __syncthreads();
    float inv = 1.f/sm[33];
    size_t off = row*T_ + tid;
    #pragma unroll
    for(int j=0;j<8;j++){
        float pv = v[j]*inv;
        bf16 h,l; bfsplit(pv, h, l);
        PH[off + j*256] = h;
        PL[off + j*256] = l;
    }
}

// ---------------- output proj + RevIN denorm ----------------
__global__ void k_final(const float* __restrict__ o, const float* __restrict__ w,
                        const float* __restrict__ ob, const float* __restrict__ rw,
                        const float* __restrict__ rb, float* __restrict__ out){
    int bt = blockIdx.x;
    int b  = bt >> 11;
    int e  = threadIdx.x;
    float x = o[(size_t)bt*E_ + e];
    float p0 = x*w[e], p1 = x*w[E_+e], p2 = x*w[2*E_+e];
    for(int s=16;s;s>>=1){
        p0 += __shfl_down_sync(0xffffffffu, p0, s);
        p1 += __shfl_down_sync(0xffffffffu, p1, s);
        p2 += __shfl_down_sync(0xffffffffu, p2, s);
    }
    __shared__ float sm[3][8];
    int wid=e>>5, lane=e&31;
    if(lane==0){ sm[0][wid]=p0; sm[1][wid]=p1; sm[2][wid]=p2; }
    __syncthreads();
    if(e < C_){
        float s=0.f;
        #pragma unroll
        for(int wdx=0;wdx<8;wdx++) s += sm[e][wdx];
        int c = e;
        float val = s + ob[c];
        val = (val - rb[c]) / rw[c];
        val = val * g_std[b*C_+c] + g_mean[b*C_+c];
        out[(size_t)bt*C_ + c] = val;
    }
}

// ---------------- host orchestration (graph-capturable) ----------------
template<int DIL>
static void launch_mid(const float* src, const float* wt, P3 bm, float* dst, int layer){
    size_t smem = (size_t)(WSZ + BN_*(128 + 14*DIL)) * sizeof(float);
    cudaFuncSetAttribute(k_conv_mid<DIL>, cudaFuncAttributeMaxDynamicSharedMemorySize, (int)smem);
    k_conv_mid<DIL><<<dim3(T_/128, B_, 3), 128, smem>>>(src, wt, bm, dst, layer);
}

extern "C" void kernel_launch(void* const* d_in, const int* in_sizes, int n_in,
                              void* d_out, int out_size){
    const float* query = (const float*)d_in[0];
    const float* key   = (const float*)d_in[1];
    const float* out_w = (const float*)d_in[20];
    const float* out_b = (const float*)d_in[21];
    const float* rw    = (const float*)d_in[22];
    const float* rb    = (const float*)d_in[23];

    float *p_qn,*p_kn,*p_h0,*p_h1,*p_wt,*p_attn,*p_o;
    bf16 *p_qh,*p_ql,*p_kh,*p_kl,*p_vth,*p_vtl,*p_ph,*p_pl;
    cudaGetSymbolAddress((void**)&p_qn,   g_qn);
    cudaGetSymbolAddress((void**)&p_kn,   g_kn);
    cudaGetSymbolAddress((void**)&p_h0,   g_h0);
    cudaGetSymbolAddress((void**)&p_h1,   g_h1);
    cudaGetSymbolAddress((void**)&p_wt,   g_wt);
    cudaGetSymbolAddress((void**)&p_qh,   g_qh);
    cudaGetSymbolAddress((void**)&p_ql,   g_ql);
    cudaGetSymbolAddress((void**)&p_kh,   g_kh);
    cudaGetSymbolAddress((void**)&p_kl,   g_kl);
    cudaGetSymbolAddress((void**)&p_vth,  g_vth);
    cudaGetSymbolAddress((void**)&p_vtl,  g_vtl);
    cudaGetSymbolAddress((void**)&p_attn, g_attn);
    cudaGetSymbolAddress((void**)&p_ph,   g_ph);
    cudaGetSymbolAddress((void**)&p_pl,   g_pl);
    cudaGetSymbolAddress((void**)&p_o,    g_o);

    P3 w_in  = {(const float*)d_in[2],  (const float*)d_in[8],  (const float*)d_in[14]};
    P3 b_in  = {(const float*)d_in[3],  (const float*)d_in[9],  (const float*)d_in[15]};
    P3 w_mid = {(const float*)d_in[4],  (const float*)d_in[10], (const float*)d_in[16]};
    P3 b_mid = {(const float*)d_in[5],  (const float*)d_in[11], (const float*)d_in[17]};
    P3 w_out = {(const float*)d_in[6],  (const float*)d_in[12], (const float*)d_in[18]};
    P3 b_out = {(const float*)d_in[7],  (const float*)d_in[13], (const float*)d_in[19]};

    k_stats<<<B_*C_, 256>>>(key);
    k_norm<<<(B_*C_*T_ + 255)/256, 256>>>(query, key, rw, rb);
    k_wtrans<<<dim3(D_, 3), 512>>>(w_mid, p_wt);

    k_conv_in<<<dim3(T_/256, B_, 3), 256>>>(p_qn, p_kn, w_in, b_in, p_h0);
    launch_mid<2 >(p_h0, p_wt, b_mid, p_h1, 0);
    launch_mid<4 >(p_h1, p_wt, b_mid, p_h0, 1);
    launch_mid<8 >(p_h0, p_wt, b_mid, p_h1, 2);
    launch_mid<16>(p_h1, p_wt, b_mid, p_h0, 3);
    launch_mid<32>(p_h0, p_wt, b_mid, p_h1, 4);
    k_conv_out<<<dim3(T_/32, B_, 3), 256>>>(p_h1, w_out, b_out,
                                            p_qh, p_ql, p_kh, p_kl, p_vth, p_vtl);

    // S = scale * Q K^T   (3xBF16 m16n8k16)
    k_mma_bf<<<dim3(T_/128, T_/128, B_), 256>>>(
        p_qh, p_ql, p_kh, p_kl, p_attn, E_,
        (size_t)T_*E_, (size_t)T_*E_, (size_t)T_*T_, T_, 0.0625f);
    k_softmax<<<B_*T_, 256>>>(p_attn, p_ph, p_pl);
    // O = P V   (same NT kernel; V pre-transposed)
    k_mma_bf<<<dim3(T_/128, E_/128, B_), 256>>>(
        p_ph, p_pl, p_vth, p_vtl, p_o, T_,
        (size_t)T_*T_, (size_t)E_*T_, (size_t)T_*E_, E_, 1.0f);
    k_final<<<B_*T_, 256>>>(p_o, out_w, out_b, rw, rb, (float*)d_out);
}

// round 13
// speedup vs baseline: 1.7450x; 1.0255x over previous
#include <cuda_runtime.h>
#include <cuda_bf16.h>
#include <math.h>
#include <stdint.h>

#define B_  8
#define T_  2048
#define C_  3
#define E_  256
#define K_  15
#define D_  5
#define BN_ 32
#define WSZ (BN_*BN_*K_)   // 15360 floats per mid layer

struct P3 { const float *q, *k, *v; };

__device__ __forceinline__ const float* pick(const P3& p, int net){
    return net==0 ? p.q : (net==1 ? p.k : p.v);
}

typedef __nv_bfloat16 bf16;

// ---------------- scratch (device globals; no allocs allowed) ----------------
static __device__ float g_mean[B_*C_];
static __device__ float g_std [B_*C_];
static __device__ float g_qn[B_*C_*T_];
static __device__ float g_kn[B_*C_*T_];
static __device__ float g_h0[3*B_*BN_*T_];
static __device__ float g_h1[3*B_*BN_*T_];
static __device__ float g_wt[3*D_*WSZ];           // mid weights transposed [rest][cout]
static __device__ __align__(16) bf16 g_qh[(size_t)B_*T_*E_];
static __device__ __align__(16) bf16 g_ql[(size_t)B_*T_*E_];
static __device__ __align__(16) bf16 g_kh[(size_t)B_*T_*E_];
static __device__ __align__(16) bf16 g_kl[(size_t)B_*T_*E_];
static __device__ __align__(16) bf16 g_vth[(size_t)B_*E_*T_];  // V^T [B][E][T]
static __device__ __align__(16) bf16 g_vtl[(size_t)B_*E_*T_];
static __device__ float g_attn[(size_t)B_*T_*T_];              // S raw (128 MiB)
static __device__ __align__(16) bf16 g_ph[(size_t)B_*T_*T_];   // P split hi
static __device__ __align__(16) bf16 g_pl[(size_t)B_*T_*T_];   // P split lo
static __device__ float g_o[(size_t)B_*T_*E_];

// ---------------- bf16 split ----------------
__device__ __forceinline__ void bfsplit(float x, bf16& h, bf16& l){
    h = __float2bfloat16_rn(x);
    l = __float2bfloat16_rn(x - __bfloat162float(h));
}

// ---------------- RevIN stats over time of key_in ----------------
__global__ void k_stats(const float* __restrict__ key){
    int bc = blockIdx.x, b = bc / C_, c = bc % C_;
    int tid = threadIdx.x;
    float s = 0.f, ss = 0.f;
    for (int t = tid; t < T_; t += 256){
        float x = key[((size_t)b*T_ + t)*C_ + c];
        s += x; ss += x*x;
    }
    __shared__ float r1[256], r2[256];
    r1[tid]=s; r2[tid]=ss; __syncthreads();
    for(int o=128;o;o>>=1){ if(tid<o){ r1[tid]+=r1[tid+o]; r2[tid]+=r2[tid+o]; } __syncthreads(); }
    if(tid==0){
        float m = r1[0]/(float)T_;
        float v = r2[0]/(float)T_ - m*m;
        g_mean[bc]=m;
        g_std[bc]=sqrtf(v + 1e-5f);
    }
}

// ---------------- normalize + transpose to [B][C][T] ----------------
__global__ void k_norm(const float* __restrict__ q, const float* __restrict__ k,
                       const float* __restrict__ rw, const float* __restrict__ rb){
    int i = blockIdx.x*256 + threadIdx.x;
    if(i >= B_*C_*T_) return;
    int t = i % T_, c = (i / T_) % C_, b = i / (C_*T_);
    float m = g_mean[b*C_+c], inv = 1.f/g_std[b*C_+c];
    float w = rw[c], bb = rb[c];
    size_t src = ((size_t)b*T_ + t)*C_ + c;
    g_qn[i] = (q[src]-m)*inv*w + bb;
    g_kn[i] = (k[src]-m)*inv*w + bb;
}

// ---------------- transpose mid weights to [ci*15+k][cout] ----------------
__global__ void k_wtrans(P3 wm, float* __restrict__ wt){
    int layer = blockIdx.x, net = blockIdx.y;
    const float* src = pick(wm, net) + (size_t)layer*WSZ;
    float* dst = wt + ((size_t)(net*D_ + layer))*WSZ;
    for(int i=threadIdx.x; i<WSZ; i+=blockDim.x){
        int cout = i/480, rest = i - cout*480;
        dst[rest*BN_ + cout] = src[i];
    }
}

// ---------------- conv in (fused q/k/v): C_ -> BN_, K=15, dil=1, relu ------
__global__ void k_conv_in(const float* __restrict__ qn, const float* __restrict__ kn,
                          P3 w, P3 bias, float* __restrict__ dstbase){
    int net = blockIdx.z;
    const float* src = (net==0) ? qn : kn;
    const float* wp  = pick(w, net);
    const float* bp  = pick(bias, net);
    float* dst = dstbase + (size_t)net*B_*BN_*T_;

    __shared__ float ws[BN_*C_*K_];
    __shared__ float bs[BN_];
    __shared__ float xs[C_][256 + K_ - 1];
    int b = blockIdx.y, t0 = blockIdx.x*256, tid = threadIdx.x;
    for(int i=tid;i<BN_*C_*K_;i+=256) ws[i]=wp[i];
    if(tid<BN_) bs[tid]=bp[tid];
    const int W = 256 + K_ - 1;
    for(int i=tid;i<C_*W;i+=256){
        int ci=i/W, p=i%W, g=t0+p-7;
        xs[ci][p] = ((unsigned)g < T_) ? src[(b*C_+ci)*T_ + g] : 0.f;
    }
    __syncthreads();
    float acc[BN_];
    #pragma unroll
    for(int c=0;c<BN_;c++) acc[c]=bs[c];
    #pragma unroll
    for(int ci=0;ci<C_;ci++){
        #pragma unroll
        for(int k=0;k<K_;k++){
            float x = xs[ci][tid+k];
            #pragma unroll
            for(int c=0;c<BN_;c++) acc[c] += x * ws[(c*C_+ci)*K_+k];
        }
    }
    int t = t0 + tid;
    #pragma unroll
    for(int c=0;c<BN_;c++) dst[((size_t)b*BN_+c)*T_ + t] = fmaxf(acc[c], 0.f);
}

// ------ conv mid (fused q/k/v, cout halves, weights in smem): dilated ------
// blockIdx.z in [0,6): net = z>>1, half = z&1. 30KB weight tile + x tile.
template<int DIL>
__global__ void __launch_bounds__(128)
k_conv_mid(const float* __restrict__ srcbase,
           const float* __restrict__ wt, P3 bm,
           float* __restrict__ dstbase, int layer){
    constexpr int W = 128 + 14*DIL;
    constexpr int H = 7*DIL;
    extern __shared__ float sm[];
    float* ws = sm;                 // 480*16 floats, layout [ci*15+k][16]
    float* xs = sm + 480*16;        // 32 * W

    int net = blockIdx.z >> 1, half = blockIdx.z & 1;
    int co0 = half * 16;
    const float* w    = wt + ((size_t)(net*D_ + layer))*WSZ;   // rows of 32
    const float* bias = pick(bm, net) + layer*BN_ + co0;
    const float* src  = srcbase + (size_t)net*B_*BN_*T_;
    float* dst        = dstbase + (size_t)net*B_*BN_*T_;

    int b = blockIdx.y, t0 = blockIdx.x*128, tid = threadIdx.x;

    // copy half of the (pre-transposed) weights: 480 rows x 16 floats
    for(int i=tid; i<480*4; i+=128){
        int row = i>>2, q = i&3;
        *(float4*)(ws + row*16 + q*4) = *(const float4*)(w + row*BN_ + co0 + q*4);
    }
    for(int i=tid;i<BN_*W;i+=128){
        int ci = i/W, p = i - ci*W, g = t0 - H + p;
        xs[i] = ((unsigned)g < T_) ? src[(b*BN_+ci)*T_ + g] : 0.f;
    }
    __syncthreads();

    float acc[16];
    #pragma unroll
    for(int c=0;c<16;c++) acc[c]=__ldg(&bias[c]);

    for(int ci=0;ci<BN_;ci++){
        const float* xr = xs + ci*W + tid;
        #pragma unroll
        for(int k=0;k<K_;k++){
            float x = xr[k*DIL];
            const float4* wr = (const float4*)(ws + (ci*K_+k)*16);
            #pragma unroll
            for(int m=0;m<4;m++){
                float4 wv = wr[m];
                acc[4*m+0] += x*wv.x;
                acc[4*m+1] += x*wv.y;
                acc[4*m+2] += x*wv.z;
                acc[4*m+3] += x*wv.w;
            }
        }
    }
    int t = t0 + tid;
    #pragma unroll
    for(int c=0;c<16;c++) dst[((size_t)b*BN_+co0+c)*T_ + t] = fmaxf(acc[c], 0.f);
}

// ------- conv out (fused, 1x1): BN_ -> E_, writes bf16-split Q/K/Vt -------
__global__ void k_conv_out(const float* __restrict__ srcbase, P3 w, P3 bias,
                           bf16* __restrict__ qh, bf16* __restrict__ ql,
                           bf16* __restrict__ kh, bf16* __restrict__ kl,
                           bf16* __restrict__ vth, bf16* __restrict__ vtl){
    int net = blockIdx.z;
    const float* src = srcbase + (size_t)net*B_*BN_*T_;
    const float* wp  = pick(w, net);
    const float* bp  = pick(bias, net);

    __shared__ float xs[BN_][32];
    int b = blockIdx.y, t0 = blockIdx.x*32, e = threadIdx.x;
    for(int i=e;i<BN_*32;i+=256){
        int ci=i>>5, tl=i&31;
        xs[ci][tl] = src[((size_t)b*BN_+ci)*T_ + t0 + tl];
    }
    __syncthreads();
    float acc[32];
    float bb = bp[e];
    #pragma unroll
    for(int t=0;t<32;t++) acc[t]=bb;
    #pragma unroll 4
    for(int ci=0;ci<BN_;ci++){
        float wv = __ldg(&wp[e*BN_+ci]);
        #pragma unroll
        for(int t=0;t<32;t++) acc[t] += xs[ci][t]*wv;
    }
    if(net < 2){
        bf16* H = net ? kh : qh;
        bf16* L = net ? kl : ql;
        #pragma unroll
        for(int t=0;t<32;t++){
            bf16 h,l; bfsplit(acc[t], h, l);
            size_t o = ((size_t)b*T_ + t0+t)*E_ + e;
            H[o]=h; L[o]=l;
        }
    } else {
        size_t o = ((size_t)b*E_ + e)*T_ + t0;
        #pragma unroll
        for(int t=0;t<32;t++){
            bf16 h,l; bfsplit(acc[t], h, l);
            vth[o+t]=h; vtl[o+t]=l;
        }
    }
}

// =========== 3xBF16 mma.sync m16n8k16 GEMM, NT form, bf16-split inputs =====
__device__ __forceinline__ void mma16(float* c, const unsigned* a, unsigned b0, unsigned b1){
    asm volatile(
        "mma.sync.aligned.m16n8k16.row.col.f32.bf16.bf16.f32 "
        "{%0,%1,%2,%3},{%4,%5,%6,%7},{%8,%9},{%0,%1,%2,%3};"
        : "+f"(c[0]), "+f"(c[1]), "+f"(c[2]), "+f"(c[3])
        : "r"(a[0]), "r"(a[1]), "r"(a[2]), "r"(a[3]), "r"(b0), "r"(b1));
}

#define SKM 136   // padded leading dim (words)

__device__ __forceinline__ void mma_chunk_bf(
    const unsigned (*AsH)[SKM], const unsigned (*AsL)[SKM],
    const unsigned (*BsH)[SKM], const unsigned (*BsL)[SKM],
    float acc[16][4], int wm, int wn, int lane)
{
    int lq = lane >> 2, lr = lane & 3;
    unsigned aH[2][4], aL[2][4];
    #pragma unroll
    for(int mt=0; mt<2; mt++){
        int rm = wm*32 + mt*16 + lq;
        aH[mt][0]=AsH[lr  ][rm];  aH[mt][1]=AsH[lr  ][rm+8];
        aH[mt][2]=AsH[lr+4][rm];  aH[mt][3]=AsH[lr+4][rm+8];
        aL[mt][0]=AsL[lr  ][rm];  aL[mt][1]=AsL[lr  ][rm+8];
        aL[mt][2]=AsL[lr+4][rm];  aL[mt][3]=AsL[lr+4][rm+8];
    }
    #pragma unroll
    for(int nt=0; nt<8; nt++){
        int cn = wn*64 + nt*8 + lq;
        unsigned bH0=BsH[lr][cn], bH1=BsH[lr+4][cn];
        unsigned bL0=BsL[lr][cn], bL1=BsL[lr+4][cn];
        #pragma unroll
        for(int mt=0; mt<2; mt++){
            mma16(acc[mt*8+nt], aH[mt], bH0, bH1);
            mma16(acc[mt*8+nt], aH[mt], bL0, bL1);
            mma16(acc[mt*8+nt], aL[mt], bH0, bH1);
        }
    }
}

// C[M,N] = alpha * A[M,K] * B[N,K]^T, A/B as bf16 hi/lo arrays (K contiguous)
__global__ void __launch_bounds__(256, 2)
k_mma_bf(const bf16* __restrict__ Ah, const bf16* __restrict__ Al,
         const bf16* __restrict__ Bh, const bf16* __restrict__ Bl,
         float* __restrict__ Cm, int Kdim,
         size_t sA, size_t sB, size_t sC, int ldC, float alpha){
    __shared__ unsigned AsH[8][SKM], AsL[8][SKM], BsH[8][SKM], BsL[8][SKM];
    int bz = blockIdx.z;
    Ah += bz*sA; Al += bz*sA;
    Bh += bz*sB; Bl += bz*sB;
    Cm += bz*sC;
    int tid = threadIdx.x, lane = tid & 31, wid = tid >> 5;
    int wm = wid & 3, wn = wid >> 2;
    int row0 = blockIdx.x*128, col0 = blockIdx.y*128;

    float acc[16][4];
    #pragma unroll
    for(int i=0;i<16;i++){ acc[i][0]=acc[i][1]=acc[i][2]=acc[i][3]=0.f; }

    int r = tid >> 1, w4 = (tid & 1) * 4;
    const unsigned* wAh = (const unsigned*)(Ah + (size_t)(row0+r)*Kdim);
    const unsigned* wAl = (const unsigned*)(Al + (size_t)(row0+r)*Kdim);
    const unsigned* wBh = (const unsigned*)(Bh + (size_t)(col0+r)*Kdim);
    const unsigned* wBl = (const unsigned*)(Bl + (size_t)(col0+r)*Kdim);

    uint4 vah, val_, vbh, vbl;
    vah = *(const uint4*)(wAh + w4);
    val_ = *(const uint4*)(wAl + w4);
    vbh = *(const uint4*)(wBh + w4);
    vbl = *(const uint4*)(wBl + w4);

    const int NCH = Kdim >> 4;
    for(int ch=0; ch<NCH; ch++){
        AsH[w4+0][r]=vah.x; AsH[w4+1][r]=vah.y; AsH[w4+2][r]=vah.z; AsH[w4+3][r]=vah.w;
        AsL[w4+0][r]=val_.x; AsL[w4+1][r]=val_.y; AsL[w4+2][r]=val_.z; AsL[w4+3][r]=val_.w;
        BsH[w4+0][r]=vbh.x; BsH[w4+1][r]=vbh.y; BsH[w4+2][r]=vbh.z; BsH[w4+3][r]=vbh.w;
        BsL[w4+0][r]=vbl.x; BsL[w4+1][r]=vbl.y; BsL[w4+2][r]=vbl.z; BsL[w4+3][r]=vbl.w;
        __syncthreads();
        if(ch+1 < NCH){
            int wo = (ch+1)*8 + w4;
            vah = *(const uint4*)(wAh + wo);
            val_ = *(const uint4*)(wAl + wo);
            vbh = *(const uint4*)(wBh + wo);
            vbl = *(const uint4*)(wBl + wo);
        }
        mma_chunk_bf(AsH, AsL, BsH, BsL, acc, wm, wn, lane);
        __syncthreads();
    }
    int lq = lane>>2, lr = lane&3;
    #pragma unroll
    for(int mt=0; mt<2; mt++){
        #pragma unroll
        for(int nt=0; nt<8; nt++){
            int row = row0 + wm*32 + mt*16 + lq;
            int col = col0 + wn*64 + nt*8 + lr*2;
            float* c = acc[mt*8+nt];
            *(float2*)(Cm + (size_t)row*ldC + col)     = make_float2(c[0]*alpha, c[1]*alpha);
            *(float2*)(Cm + (size_t)(row+8)*ldC + col) = make_float2(c[2]*alpha, c[3]*alpha);
        }
    }
}

// ---------------- row softmax over T_, writes bf16-split P ----------------
__global__ void k_softmax(const float* __restrict__ S, bf16* __restrict__ PH,
                          bf16* __restrict__ PL){
    size_t row = blockIdx.x;
    const float* p = S + row*T_;
    int tid = threadIdx.x;
    float v[8];
    #pragma unroll
    for(int j=0;j<8;j++) v[j] = p[tid + j*256];
    float m = v[0];
    #pragma unroll
    for(int j=1;j<8;j++) m = fmaxf(m, v[j]);
    __shared__ float sm[40];
    for(int o=16;o;o>>=1) m = fmaxf(m, __shfl_xor_sync(0xffffffffu, m, o));
    if((tid&31)==0) sm[tid>>5] = m;
    __syncthreads();
    if(tid<32){
        float t = (tid<8)?sm[tid]:-3.0e38f;
        for(int o=4;o;o>>=1) t=fmaxf(t,__shfl_xor_sync(0xffffffffu,t,o));
        if(tid==0) sm[32]=t;
    }
    __syncthreads();
    m = sm[32];
    float s=0.f;
    #pragma unroll
    for(int j=0;j<8;j++){ v[j]=__expf(v[j]-m); s+=v[j]; }
    for(int o=16;o;o>>=1) s += __shfl_xor_sync(0xffffffffu, s, o);
    if((tid&31)==0) sm[tid>>5] = s;
    __syncthreads();
    if(tid<32){
        float t=(tid<8)?sm[tid]:0.f;
        for(int o=4;o;o>>=1) t+=__shfl_xor_sync(0xffffffffu,t,o);
        if(tid==0) sm[33]=t;
    }
    __syncthreads();
    float inv = 1.f/sm[33];
    size_t off = row*T_ + tid;
    #pragma unroll
    for(int j=0;j<8;j++){
        float pv = v[j]*inv;
        bf16 h,l; bfsplit(pv, h, l);
        PH[off + j*256] = h;
        PL[off + j*256] = l;
    }
}

// ---------------- output proj + RevIN denorm ----------------
__global__ void k_final(const float* __restrict__ o, const float* __restrict__ w,
                        const float* __restrict__ ob, const float* __restrict__ rw,
                        const float* __restrict__ rb, float* __restrict__ out){
    int bt = blockIdx.x;
    int b  = bt >> 11;
    int e  = threadIdx.x;
    float x = o[(size_t)bt*E_ + e];
    float p0 = x*w[e], p1 = x*w[E_+e], p2 = x*w[2*E_+e];
    for(int s=16;s;s>>=1){
        p0 += __shfl_down_sync(0xffffffffu, p0, s);
        p1 += __shfl_down_sync(0xffffffffu, p1, s);
        p2 += __shfl_down_sync(0xffffffffu, p2, s);
    }
    __shared__ float sm[3][8];
    int wid=e>>5, lane=e&31;
    if(lane==0){ sm[0][wid]=p0; sm[1][wid]=p1; sm[2][wid]=p2; }
    __syncthreads();
    if(e < C_){
        float s=0.f;
        #pragma unroll
        for(int wdx=0;wdx<8;wdx++) s += sm[e][wdx];
        int c = e;
        float val = s + ob[c];
        val = (val - rb[c]) / rw[c];
        val = val * g_std[b*C_+c] + g_mean[b*C_+c];
        out[(size_t)bt*C_ + c] = val;
    }
}

// ---------------- host orchestration (graph-capturable) ----------------
template<int DIL>
static void launch_mid(const float* src, const float* wt, P3 bm, float* dst, int layer){
    size_t smem = (size_t)(480*16 + BN_*(128 + 14*DIL)) * sizeof(float);
    cudaFuncSetAttribute(k_conv_mid<DIL>, cudaFuncAttributeMaxDynamicSharedMemorySize, (int)smem);
    k_conv_mid<DIL><<<dim3(T_/128, B_, 6), 128, smem>>>(src, wt, bm, dst, layer);
}

extern "C" void kernel_launch(void* const* d_in, const int* in_sizes, int n_in,
                              void* d_out, int out_size){
    const float* query = (const float*)d_in[0];
    const float* key   = (const float*)d_in[1];
    const float* out_w = (const float*)d_in[20];
    const float* out_b = (const float*)d_in[21];
    const float* rw    = (const float*)d_in[22];
    const float* rb    = (const float*)d_in[23];

    float *p_qn,*p_kn,*p_h0,*p_h1,*p_wt,*p_attn,*p_o;
    bf16 *p_qh,*p_ql,*p_kh,*p_kl,*p_vth,*p_vtl,*p_ph,*p_pl;
    cudaGetSymbolAddress((void**)&p_qn,   g_qn);
    cudaGetSymbolAddress((void**)&p_kn,   g_kn);
    cudaGetSymbolAddress((void**)&p_h0,   g_h0);
    cudaGetSymbolAddress((void**)&p_h1,   g_h1);
    cudaGetSymbolAddress((void**)&p_wt,   g_wt);
    cudaGetSymbolAddress((void**)&p_qh,   g_qh);
    cudaGetSymbolAddress((void**)&p_ql,   g_ql);
    cudaGetSymbolAddress((void**)&p_kh,   g_kh);
    cudaGetSymbolAddress((void**)&p_kl,   g_kl);
    cudaGetSymbolAddress((void**)&p_vth,  g_vth);
    cudaGetSymbolAddress((void**)&p_vtl,  g_vtl);
    cudaGetSymbolAddress((void**)&p_attn, g_attn);
    cudaGetSymbolAddress((void**)&p_ph,   g_ph);
    cudaGetSymbolAddress((void**)&p_pl,   g_pl);
    cudaGetSymbolAddress((void**)&p_o,    g_o);

    P3 w_in  = {(const float*)d_in[2],  (const float*)d_in[8],  (const float*)d_in[14]};
    P3 b_in  = {(const float*)d_in[3],  (const float*)d_in[9],  (const float*)d_in[15]};
    P3 w_mid = {(const float*)d_in[4],  (const float*)d_in[10], (const float*)d_in[16]};
    P3 b_mid = {(const float*)d_in[5],  (const float*)d_in[11], (const float*)d_in[17]};
    P3 w_out = {(const float*)d_in[6],  (const float*)d_in[12], (const float*)d_in[18]};
    P3 b_out = {(const float*)d_in[7],  (const float*)d_in[13], (const float*)d_in[19]};

    k_stats<<<B_*C_, 256>>>(key);
    k_norm<<<(B_*C_*T_ + 255)/256, 256>>>(query, key, rw, rb);
    k_wtrans<<<dim3(D_, 3), 512>>>(w_mid, p_wt);

    k_conv_in<<<dim3(T_/256, B_, 3), 256>>>(p_qn, p_kn, w_in, b_in, p_h0);
    launch_mid<2 >(p_h0, p_wt, b_mid, p_h1, 0);
    launch_mid<4 >(p_h1, p_wt, b_mid, p_h0, 1);
    launch_mid<8 >(p_h0, p_wt, b_mid, p_h1, 2);
    launch_mid<16>(p_h1, p_wt, b_mid, p_h0, 3);
    launch_mid<32>(p_h0, p_wt, b_mid, p_h1, 4);
    k_conv_out<<<dim3(T_/32, B_, 3), 256>>>(p_h1, w_out, b_out,
                                            p_qh, p_ql, p_kh, p_kl, p_vth, p_vtl);

    // S = scale * Q K^T   (3xBF16 m16n8k16)
    k_mma_bf<<<dim3(T_/128, T_/128, B_), 256>>>(
        p_qh, p_ql, p_kh, p_kl, p_attn, E_,
        (size_t)T_*E_, (size_t)T_*E_, (size_t)T_*T_, T_, 0.0625f);
    k_softmax<<<B_*T_, 256>>>(p_attn, p_ph, p_pl);
    // O = P V   (same NT kernel; V pre-transposed)
    k_mma_bf<<<dim3(T_/128, E_/128, B_), 256>>>(
        p_ph, p_pl, p_vth, p_vtl, p_o, T_,
        (size_t)T_*T_, (size_t)E_*T_, (size_t)T_*E_, E_, 1.0f);
    k_final<<<B_*T_, 256>>>(p_o, out_w, out_b, rw, rb, (float*)d_out);
}

// round 14
// speedup vs baseline: 2.3041x; 1.3204x over previous
#include <cuda_runtime.h>
#include <cuda_bf16.h>
#include <math.h>
#include <stdint.h>

#define B_  8
#define T_  2048
#define C_  3
#define E_  256
#define K_  15
#define D_  5
#define BN_ 32
#define WSZ (BN_*BN_*K_)   // 15360 floats per mid layer

struct P3 { const float *q, *k, *v; };

__device__ __forceinline__ const float* pick(const P3& p, int net){
    return net==0 ? p.q : (net==1 ? p.k : p.v);
}

typedef __nv_bfloat16 bf16;

// ---------------- scratch (device globals; no allocs allowed) ----------------
static __device__ float g_mean[B_*C_];
static __device__ float g_std [B_*C_];
static __device__ float g_qn[B_*C_*T_];
static __device__ float g_kn[B_*C_*T_];
static __device__ float g_h0[3*B_*BN_*T_];
static __device__ float g_h1[3*B_*BN_*T_];
// pre-fragmented mid-conv weights (mma A-fragment layout), bf16 hi/lo words
static __device__ __align__(16) unsigned g_wfH[3*D_*15*2*2*32*4];
static __device__ __align__(16) unsigned g_wfL[3*D_*15*2*2*32*4];
static __device__ __align__(16) bf16 g_qh[(size_t)B_*T_*E_];
static __device__ __align__(16) bf16 g_ql[(size_t)B_*T_*E_];
static __device__ __align__(16) bf16 g_kh[(size_t)B_*T_*E_];
static __device__ __align__(16) bf16 g_kl[(size_t)B_*T_*E_];
static __device__ __align__(16) bf16 g_vth[(size_t)B_*E_*T_];  // V^T [B][E][T]
static __device__ __align__(16) bf16 g_vtl[(size_t)B_*E_*T_];
static __device__ float g_attn[(size_t)B_*T_*T_];              // S raw (128 MiB)
static __device__ __align__(16) bf16 g_ph[(size_t)B_*T_*T_];   // P split hi
static __device__ __align__(16) bf16 g_pl[(size_t)B_*T_*T_];   // P split lo
static __device__ float g_o[(size_t)B_*T_*E_];

// ---------------- bf16 split ----------------
__device__ __forceinline__ void bfsplit(float x, bf16& h, bf16& l){
    h = __float2bfloat16_rn(x);
    l = __float2bfloat16_rn(x - __bfloat162float(h));
}

// ---------------- RevIN stats over time of key_in ----------------
__global__ void k_stats(const float* __restrict__ key){
    int bc = blockIdx.x, b = bc / C_, c = bc % C_;
    int tid = threadIdx.x;
    float s = 0.f, ss = 0.f;
    for (int t = tid; t < T_; t += 256){
        float x = key[((size_t)b*T_ + t)*C_ + c];
        s += x; ss += x*x;
    }
    __shared__ float r1[256], r2[256];
    r1[tid]=s; r2[tid]=ss; __syncthreads();
    for(int o=128;o;o>>=1){ if(tid<o){ r1[tid]+=r1[tid+o]; r2[tid]+=r2[tid+o]; } __syncthreads(); }
    if(tid==0){
        float m = r1[0]/(float)T_;
        float v = r2[0]/(float)T_ - m*m;
        g_mean[bc]=m;
        g_std[bc]=sqrtf(v + 1e-5f);
    }
}

// ---------------- normalize + transpose to [B][C][T] ----------------
__global__ void k_norm(const float* __restrict__ q, const float* __restrict__ k,
                       const float* __restrict__ rw, const float* __restrict__ rb){
    int i = blockIdx.x*256 + threadIdx.x;
    if(i >= B_*C_*T_) return;
    int t = i % T_, c = (i / T_) % C_, b = i / (C_*T_);
    float m = g_mean[b*C_+c], inv = 1.f/g_std[b*C_+c];
    float w = rw[c], bb = rb[c];
    size_t src = ((size_t)b*T_ + t)*C_ + c;
    g_qn[i] = (q[src]-m)*inv*w + bb;
    g_kn[i] = (k[src]-m)*inv*w + bb;
}

// ------ pre-fragment mid weights into mma A layout (bf16 hi/lo words) ------
// idx = ((((net*D+layer)*15 + k)*2 + mt)*2 + cc)*32 + lane ; 4 words per lane.
__global__ void k_wfrag(P3 wm, unsigned* __restrict__ wfH, unsigned* __restrict__ wfL){
    int k = blockIdx.x, layer = blockIdx.y, net = blockIdx.z;
    int tid = threadIdx.x;
    int lane = tid & 31, wid = tid >> 5;
    int mt = wid >> 1, cc = wid & 1;
    int lq = lane >> 2, lr = lane & 3;
    const float* w = pick(wm, net) + (size_t)layer*WSZ;  // [cout][ci][k]
    int r0 = mt*16 + lq, r1 = r0 + 8;
    int cb = cc*16 + 2*lr;
    int rows[4] = {r0, r1, r0, r1};
    int cols[4] = {cb, cb, cb+8, cb+8};
    unsigned hw[4], lw[4];
    #pragma unroll
    for(int j=0;j<4;j++){
        float v0 = w[(rows[j]*32 + cols[j])*15 + k];
        float v1 = w[(rows[j]*32 + cols[j]+1)*15 + k];
        bf16 h0,l0,h1,l1;
        bfsplit(v0,h0,l0); bfsplit(v1,h1,l1);
        hw[j] = (unsigned)__bfloat16_as_ushort(h0) | ((unsigned)__bfloat16_as_ushort(h1)<<16);
        lw[j] = (unsigned)__bfloat16_as_ushort(l0) | ((unsigned)__bfloat16_as_ushort(l1)<<16);
    }
    int idx = ((((net*D_ + layer)*15 + k)*2 + mt)*2 + cc)*32 + lane;
    ((uint4*)wfH)[idx] = make_uint4(hw[0],hw[1],hw[2],hw[3]);
    ((uint4*)wfL)[idx] = make_uint4(lw[0],lw[1],lw[2],lw[3]);
}

// ---------------- conv in (fused q/k/v): C_ -> BN_, K=15, dil=1, relu ------
__global__ void k_conv_in(const float* __restrict__ qn, const float* __restrict__ kn,
                          P3 w, P3 bias, float* __restrict__ dstbase){
    int net = blockIdx.z;
    const float* src = (net==0) ? qn : kn;
    const float* wp  = pick(w, net);
    const float* bp  = pick(bias, net);
    float* dst = dstbase + (size_t)net*B_*BN_*T_;

    __shared__ float ws[BN_*C_*K_];
    __shared__ float bs[BN_];
    __shared__ float xs[C_][256 + K_ - 1];
    int b = blockIdx.y, t0 = blockIdx.x*256, tid = threadIdx.x;
    for(int i=tid;i<BN_*C_*K_;i+=256) ws[i]=wp[i];
    if(tid<BN_) bs[tid]=bp[tid];
    const int W = 256 + K_ - 1;
    for(int i=tid;i<C_*W;i+=256){
        int ci=i/W, p=i%W, g=t0+p-7;
        xs[ci][p] = ((unsigned)g < T_) ? src[(b*C_+ci)*T_ + g] : 0.f;
    }
    __syncthreads();
    float acc[BN_];
    #pragma unroll
    for(int c=0;c<BN_;c++) acc[c]=bs[c];
    #pragma unroll
    for(int ci=0;ci<C_;ci++){
        #pragma unroll
        for(int k=0;k<K_;k++){
            float x = xs[ci][tid+k];
            #pragma unroll
            for(int c=0;c<BN_;c++) acc[c] += x * ws[(c*C_+ci)*K_+k];
        }
    }
    int t = t0 + tid;
    #pragma unroll
    for(int c=0;c<BN_;c++) dst[((size_t)b*BN_+c)*T_ + t] = fmaxf(acc[c], 0.f);
}

// ------ conv mid via tensor cores: 3xBF16 m16n8k16, dilated-shift B ------
// Block: 128 thr = 4 warps = (mt: 16-cout tile) x (nh: 64-t half). Output 32x128.
// x tile staged t-major [t][ci] bf16 hi/lo, pitch 36 bf16 (conflict-free).
template<int DIL>
__global__ void __launch_bounds__(128)
k_conv_mma(const float* __restrict__ srcbase, const unsigned* __restrict__ wfH,
           const unsigned* __restrict__ wfL, P3 bm,
           float* __restrict__ dstbase, int layer){
    constexpr int TW  = 128 + 14*DIL;
    constexpr int H   = 7*DIL;
    constexpr int RPB = 36;                // bf16 per staged row (32 + pad)
    extern __shared__ bf16 xsm[];
    bf16* xh = xsm;
    bf16* xl = xsm + TW*RPB;

    int net = blockIdx.z, b = blockIdx.y, t0 = blockIdx.x*128, tid = threadIdx.x;
    const float* src = srcbase + ((size_t)net*B_ + b)*BN_*T_;
    float* dst       = dstbase + ((size_t)net*B_ + b)*BN_*T_;

    // stage x tile: [p in t-space][ci], bf16 hi/lo
    for(int i=tid; i<BN_*TW; i+=128){
        int ci = i / TW, p = i - ci*TW;
        int g = t0 - H + p;
        float v = ((unsigned)g < T_) ? src[ci*T_ + g] : 0.f;
        bf16 h, l; bfsplit(v, h, l);
        xh[p*RPB + ci] = h;
        xl[p*RPB + ci] = l;
    }
    __syncthreads();

    int lane = tid & 31, wid = tid >> 5;
    int mt = wid >> 1, nh = wid & 1;
    int lq = lane >> 2, lr = lane & 3;

    float acc[8][4] = {};
    int nl = (net*D_ + layer)*15;
    const uint4* fH = (const uint4*)wfH;
    const uint4* fL = (const uint4*)wfL;

    for(int k=0; k<K_; k++){
        int fi = (nl + k)*4 + mt*2;
        uint4 ah0 = __ldg(&fH[(fi+0)*32 + lane]);
        uint4 al0 = __ldg(&fL[(fi+0)*32 + lane]);
        uint4 ah1 = __ldg(&fH[(fi+1)*32 + lane]);
        uint4 al1 = __ldg(&fL[(fi+1)*32 + lane]);
        int rbase = nh*64 + lq + k*DIL;
        #pragma unroll
        for(int cc=0; cc<2; cc++){
            const unsigned* Ah = cc ? (const unsigned*)&ah1 : (const unsigned*)&ah0;
            const unsigned* Al = cc ? (const unsigned*)&al1 : (const unsigned*)&al0;
            #pragma unroll
            for(int n=0;n<8;n++){
                const bf16* rh = xh + (rbase + n*8)*RPB + cc*16;
                const bf16* rl = xl + (rbase + n*8)*RPB + cc*16;
                unsigned bh0 = *(const unsigned*)(rh + 2*lr);
                unsigned bh1 = *(const unsigned*)(rh + 2*lr + 8);
                unsigned bl0 = *(const unsigned*)(rl + 2*lr);
                unsigned bl1 = *(const unsigned*)(rl + 2*lr + 8);
                asm volatile(
                    "mma.sync.aligned.m16n8k16.row.col.f32.bf16.bf16.f32 "
                    "{%0,%1,%2,%3},{%4,%5,%6,%7},{%8,%9},{%0,%1,%2,%3};"
                    : "+f"(acc[n][0]), "+f"(acc[n][1]), "+f"(acc[n][2]), "+f"(acc[n][3])
                    : "r"(Ah[0]), "r"(Ah[1]), "r"(Ah[2]), "r"(Ah[3]), "r"(bh0), "r"(bh1));
                asm volatile(
                    "mma.sync.aligned.m16n8k16.row.col.f32.bf16.bf16.f32 "
                    "{%0,%1,%2,%3},{%4,%5,%6,%7},{%8,%9},{%0,%1,%2,%3};"
                    : "+f"(acc[n][0]), "+f"(acc[n][1]), "+f"(acc[n][2]), "+f"(acc[n][3])
                    : "r"(Ah[0]), "r"(Ah[1]), "r"(Ah[2]), "r"(Ah[3]), "r"(bl0), "r"(bl1));
                asm volatile(
                    "mma.sync.aligned.m16n8k16.row.col.f32.bf16.bf16.f32 "
                    "{%0,%1,%2,%3},{%4,%5,%6,%7},{%8,%9},{%0,%1,%2,%3};"
                    : "+f"(acc[n][0]), "+f"(acc[n][1]), "+f"(acc[n][2]), "+f"(acc[n][3])
                    : "r"(Al[0]), "r"(Al[1]), "r"(Al[2]), "r"(Al[3]), "r"(bh0), "r"(bh1));
            }
        }
    }

    const float* bias = pick(bm, net) + layer*BN_ + mt*16;
    float b0 = __ldg(&bias[lq]), b1 = __ldg(&bias[lq+8]);
    int r0 = mt*16 + lq, r1 = r0 + 8;
    #pragma unroll
    for(int n=0;n<8;n++){
        int t = t0 + nh*64 + n*8 + 2*lr;
        float2 v0 = make_float2(fmaxf(acc[n][0]+b0,0.f), fmaxf(acc[n][1]+b0,0.f));
        float2 v1 = make_float2(fmaxf(acc[n][2]+b1,0.f), fmaxf(acc[n][3]+b1,0.f));
        *(float2*)(dst + (size_t)r0*T_ + t) = v0;
        *(float2*)(dst + (size_t)r1*T_ + t) = v1;
    }
}

// ------- conv out (fused, 1x1): BN_ -> E_, writes bf16-split Q/K/Vt -------
__global__ void k_conv_out(const float* __restrict__ srcbase, P3 w, P3 bias,
                           bf16* __restrict__ qh, bf16* __restrict__ ql,
                           bf16* __restrict__ kh, bf16* __restrict__ kl,
                           bf16* __restrict__ vth, bf16* __restrict__ vtl){
    int net = blockIdx.z;
    const float* src = srcbase + (size_t)net*B_*BN_*T_;
    const float* wp  = pick(w, net);
    const float* bp  = pick(bias, net);

    __shared__ float xs[BN_][32];
    int b = blockIdx.y, t0 = blockIdx.x*32, e = threadIdx.x;
    for(int i=e;i<BN_*32;i+=256){
        int ci=i>>5, tl=i&31;
        xs[ci][tl] = src[((size_t)b*BN_+ci)*T_ + t0 + tl];
    }
    __syncthreads();
    float acc[32];
    float bb = bp[e];
    #pragma unroll
    for(int t=0;t<32;t++) acc[t]=bb;
    #pragma unroll 4
    for(int ci=0;ci<BN_;ci++){
        float wv = __ldg(&wp[e*BN_+ci]);
        #pragma unroll
        for(int t=0;t<32;t++) acc[t] += xs[ci][t]*wv;
    }
    if(net < 2){
        bf16* H = net ? kh : qh;
        bf16* L = net ? kl : ql;
        #pragma unroll
        for(int t=0;t<32;t++){
            bf16 h,l; bfsplit(acc[t], h, l);
            size_t o = ((size_t)b*T_ + t0+t)*E_ + e;
            H[o]=h; L[o]=l;
        }
    } else {
        size_t o = ((size_t)b*E_ + e)*T_ + t0;
        #pragma unroll
        for(int t=0;t<32;t++){
            bf16 h,l; bfsplit(acc[t], h, l);
            vth[o+t]=h; vtl[o+t]=l;
        }
    }
}

// =========== 3xBF16 mma.sync m16n8k16 GEMM, NT form, bf16-split inputs =====
__device__ __forceinline__ void mma16(float* c, const unsigned* a, unsigned b0, unsigned b1){
    asm volatile(
        "mma.sync.aligned.m16n8k16.row.col.f32.bf16.bf16.f32 "
        "{%0,%1,%2,%3},{%4,%5,%6,%7},{%8,%9},{%0,%1,%2,%3};"
        : "+f"(c[0]), "+f"(c[1]), "+f"(c[2]), "+f"(c[3])
        : "r"(a[0]), "r"(a[1]), "r"(a[2]), "r"(a[3]), "r"(b0), "r"(b1));
}

#define SKM 136   // padded leading dim (words)

__device__ __forceinline__ void mma_chunk_bf(
    const unsigned (*AsH)[SKM], const unsigned (*AsL)[SKM],
    const unsigned (*BsH)[SKM], const unsigned (*BsL)[SKM],
    float acc[16][4], int wm, int wn, int lane)
{
    int lq = lane >> 2, lr = lane & 3;
    unsigned aH[2][4], aL[2][4];
    #pragma unroll
    for(int mt=0; mt<2; mt++){
        int rm = wm*32 + mt*16 + lq;
        aH[mt][0]=AsH[lr  ][rm];  aH[mt][1]=AsH[lr  ][rm+8];
        aH[mt][2]=AsH[lr+4][rm];  aH[mt][3]=AsH[lr+4][rm+8];
        aL[mt][0]=AsL[lr  ][rm];  aL[mt][1]=AsL[lr  ][rm+8];
        aL[mt][2]=AsL[lr+4][rm];  aL[mt][3]=AsL[lr+4][rm+8];
    }
    #pragma unroll
    for(int nt=0; nt<8; nt++){
        int cn = wn*64 + nt*8 + lq;
        unsigned bH0=BsH[lr][cn], bH1=BsH[lr+4][cn];
        unsigned bL0=BsL[lr][cn], bL1=BsL[lr+4][cn];
        #pragma unroll
        for(int mt=0; mt<2; mt++){
            mma16(acc[mt*8+nt], aH[mt], bH0, bH1);
            mma16(acc[mt*8+nt], aH[mt], bL0, bL1);
            mma16(acc[mt*8+nt], aL[mt], bH0, bH1);
        }
    }
}

// C[M,N] = alpha * A[M,K] * B[N,K]^T, A/B as bf16 hi/lo arrays (K contiguous)
__global__ void __launch_bounds__(256, 2)
k_mma_bf(const bf16* __restrict__ Ah, const bf16* __restrict__ Al,
         const bf16* __restrict__ Bh, const bf16* __restrict__ Bl,
         float* __restrict__ Cm, int Kdim,
         size_t sA, size_t sB, size_t sC, int ldC, float alpha){
    __shared__ unsigned AsH[8][SKM], AsL[8][SKM], BsH[8][SKM], BsL[8][SKM];
    int bz = blockIdx.z;
    Ah += bz*sA; Al += bz*sA;
    Bh += bz*sB; Bl += bz*sB;
    Cm += bz*sC;
    int tid = threadIdx.x, lane = tid & 31, wid = tid >> 5;
    int wm = wid & 3, wn = wid >> 2;
    int row0 = blockIdx.x*128, col0 = blockIdx.y*128;

    float acc[16][4];
    #pragma unroll
    for(int i=0;i<16;i++){ acc[i][0]=acc[i][1]=acc[i][2]=acc[i][3]=0.f; }

    int r = tid >> 1, w4 = (tid & 1) * 4;
    const unsigned* wAh = (const unsigned*)(Ah + (size_t)(row0+r)*Kdim);
    const unsigned* wAl = (const unsigned*)(Al + (size_t)(row0+r)*Kdim);
    const unsigned* wBh = (const unsigned*)(Bh + (size_t)(col0+r)*Kdim);
    const unsigned* wBl = (const unsigned*)(Bl + (size_t)(col0+r)*Kdim);

    uint4 vah, val_, vbh, vbl;
    vah = *(const uint4*)(wAh + w4);
    val_ = *(const uint4*)(wAl + w4);
    vbh = *(const uint4*)(wBh + w4);
    vbl = *(const uint4*)(wBl + w4);

    const int NCH = Kdim >> 4;
    for(int ch=0; ch<NCH; ch++){
        AsH[w4+0][r]=vah.x; AsH[w4+1][r]=vah.y; AsH[w4+2][r]=vah.z; AsH[w4+3][r]=vah.w;
        AsL[w4+0][r]=val_.x; AsL[w4+1][r]=val_.y; AsL[w4+2][r]=val_.z; AsL[w4+3][r]=val_.w;
        BsH[w4+0][r]=vbh.x; BsH[w4+1][r]=vbh.y; BsH[w4+2][r]=vbh.z; BsH[w4+3][r]=vbh.w;
        BsL[w4+0][r]=vbl.x; BsL[w4+1][r]=vbl.y; BsL[w4+2][r]=vbl.z; BsL[w4+3][r]=vbl.w;
        __syncthreads();
        if(ch+1 < NCH){
            int wo = (ch+1)*8 + w4;
            vah = *(const uint4*)(wAh + wo);
            val_ = *(const uint4*)(wAl + wo);
            vbh = *(const uint4*)(wBh + wo);
            vbl = *(const uint4*)(wBl + wo);
        }
        mma_chunk_bf(AsH, AsL, BsH, BsL, acc, wm, wn, lane);
        __syncthreads();
    }
    int lq = lane>>2, lr = lane&3;
    #pragma unroll
    for(int mt=0; mt<2; mt++){
        #pragma unroll
        for(int nt=0; nt<8; nt++){
            int row = row0 + wm*32 + mt*16 + lq;
            int col = col0 + wn*64 + nt*8 + lr*2;
            float* c = acc[mt*8+nt];
            *(float2*)(Cm + (size_t)row*ldC + col)     = make_float2(c[0]*alpha, c[1]*alpha);
            *(float2*)(Cm + (size_t)(row+8)*ldC + col) = make_float2(c[2]*alpha, c[3]*alpha);
        }
    }
}

// ---------------- row softmax over T_, writes bf16-split P ----------------
__global__ void k_softmax(const float* __restrict__ S, bf16* __restrict__ PH,
                          bf16* __restrict__ PL){
    size_t row = blockIdx.x;
    const float* p = S + row*T_;
    int tid = threadIdx.x;
    float v[8];
    #pragma unroll
    for(int j=0;j<8;j++) v[j] = p[tid + j*256];
    float m = v[0];
    #pragma unroll
    for(int j=1;j<8;j++) m = fmaxf(m, v[j]);
    __shared__ float sm[40];
    for(int o=16;o;o>>=1) m = fmaxf(m, __shfl_xor_sync(0xffffffffu, m, o));
    if((tid&31)==0) sm[tid>>5] = m;
    __syncthreads();
    if(tid<32){
        float t = (tid<8)?sm[tid]:-3.0e38f;
        for(int o=4;o;o>>=1) t=fmaxf(t,__shfl_xor_sync(0xffffffffu,t,o));
        if(tid==0) sm[32]=t;
    }
    __syncthreads();
    m = sm[32];
    float s=0.f;
    #pragma unroll
    for(int j=0;j<8;j++){ v[j]=__expf(v[j]-m); s+=v[j]; }
    for(int o=16;o;o>>=1) s += __shfl_xor_sync(0xffffffffu, s, o);
    if((tid&31)==0) sm[tid>>5] = s;
    __syncthreads();
    if(tid<32){
        float t=(tid<8)?sm[tid]:0.f;
        for(int o=4;o;o>>=1) t+=__shfl_xor_sync(0xffffffffu,t,o);
        if(tid==0) sm[33]=t;
    }
    __syncthreads();
    float inv = 1.f/sm[33];
    size_t off = row*T_ + tid;
    #pragma unroll
    for(int j=0;j<8;j++){
        float pv = v[j]*inv;
        bf16 h,l; bfsplit(pv, h, l);
        PH[off + j*256] = h;
        PL[off + j*256] = l;
    }
}

// ---------------- output proj + RevIN denorm ----------------
__global__ void k_final(const float* __restrict__ o, const float* __restrict__ w,
                        const float* __restrict__ ob, const float* __restrict__ rw,
                        const float* __restrict__ rb, float* __restrict__ out){
    int bt = blockIdx.x;
    int b  = bt >> 11;
    int e  = threadIdx.x;
    float x = o[(size_t)bt*E_ + e];
    float p0 = x*w[e], p1 = x*w[E_+e], p2 = x*w[2*E_+e];
    for(int s=16;s;s>>=1){
        p0 += __shfl_down_sync(0xffffffffu, p0, s);
        p1 += __shfl_down_sync(0xffffffffu, p1, s);
        p2 += __shfl_down_sync(0xffffffffu, p2, s);
    }
    __shared__ float sm[3][8];
    int wid=e>>5, lane=e&31;
    if(lane==0){ sm[0][wid]=p0; sm[1][wid]=p1; sm[2][wid]=p2; }
    __syncthreads();
    if(e < C_){
        float s=0.f;
        #pragma unroll
        for(int wdx=0;wdx<8;wdx++) s += sm[e][wdx];
        int c = e;
        float val = s + ob[c];
        val = (val - rb[c]) / rw[c];
        val = val * g_std[b*C_+c] + g_mean[b*C_+c];
        out[(size_t)bt*C_ + c] = val;
    }
}

// ---------------- host orchestration (graph-capturable) ----------------
template<int DIL>
static void launch_mid(const float* src, const unsigned* wfH, const unsigned* wfL,
                       P3 bm, float* dst, int layer){
    constexpr int TW = 128 + 14*DIL;
    size_t smem = (size_t)TW * 36 * 2 * sizeof(bf16);   // xh + xl
    cudaFuncSetAttribute(k_conv_mma<DIL>, cudaFuncAttributeMaxDynamicSharedMemorySize, (int)smem);
    k_conv_mma<DIL><<<dim3(T_/128, B_, 3), 128, smem>>>(src, wfH, wfL, bm, dst, layer);
}

extern "C" void kernel_launch(void* const* d_in, const int* in_sizes, int n_in,
                              void* d_out, int out_size){
    const float* query = (const float*)d_in[0];
    const float* key   = (const float*)d_in[1];
    const float* out_w = (const float*)d_in[20];
    const float* out_b = (const float*)d_in[21];
    const float* rw    = (const float*)d_in[22];
    const float* rb    = (const float*)d_in[23];

    float *p_qn,*p_kn,*p_h0,*p_h1,*p_attn,*p_o;
    unsigned *p_wfH,*p_wfL;
    bf16 *p_qh,*p_ql,*p_kh,*p_kl,*p_vth,*p_vtl,*p_ph,*p_pl;
    cudaGetSymbolAddress((void**)&p_qn,   g_qn);
    cudaGetSymbolAddress((void**)&p_kn,   g_kn);
    cudaGetSymbolAddress((void**)&p_h0,   g_h0);
    cudaGetSymbolAddress((void**)&p_h1,   g_h1);
    cudaGetSymbolAddress((void**)&p_wfH,  g_wfH);
    cudaGetSymbolAddress((void**)&p_wfL,  g_wfL);
    cudaGetSymbolAddress((void**)&p_qh,   g_qh);
    cudaGetSymbolAddress((void**)&p_ql,   g_ql);
    cudaGetSymbolAddress((void**)&p_kh,   g_kh);
    cudaGetSymbolAddress((void**)&p_kl,   g_kl);
    cudaGetSymbolAddress((void**)&p_vth,  g_vth);
    cudaGetSymbolAddress((void**)&p_vtl,  g_vtl);
    cudaGetSymbolAddress((void**)&p_attn, g_attn);
    cudaGetSymbolAddress((void**)&p_ph,   g_ph);
    cudaGetSymbolAddress((void**)&p_pl,   g_pl);
    cudaGetSymbolAddress((void**)&p_o,    g_o);

    P3 w_in  = {(const float*)d_in[2],  (const float*)d_in[8],  (const float*)d_in[14]};
    P3 b_in  = {(const float*)d_in[3],  (const float*)d_in[9],  (const float*)d_in[15]};
    P3 w_mid = {(const float*)d_in[4],  (const float*)d_in[10], (const float*)d_in[16]};
    P3 b_mid = {(const float*)d_in[5],  (const float*)d_in[11], (const float*)d_in[17]};
    P3 w_out = {(const float*)d_in[6],  (const float*)d_in[12], (const float*)d_in[18]};
    P3 b_out = {(const float*)d_in[7],  (const float*)d_in[13], (const float*)d_in[19]};

    k_stats<<<B_*C_, 256>>>(key);
    k_norm<<<(B_*C_*T_ + 255)/256, 256>>>(query, key, rw, rb);
    k_wfrag<<<dim3(15, D_, 3), 128>>>(w_mid, p_wfH, p_wfL);

    k_conv_in<<<dim3(T_/256, B_, 3), 256>>>(p_qn, p_kn, w_in, b_in, p_h0);
    launch_mid<2 >(p_h0, p_wfH, p_wfL, b_mid, p_h1, 0);
    launch_mid<4 >(p_h1, p_wfH, p_wfL, b_mid, p_h0, 1);
    launch_mid<8 >(p_h0, p_wfH, p_wfL, b_mid, p_h1, 2);
    launch_mid<16>(p_h1, p_wfH, p_wfL, b_mid, p_h0, 3);
    launch_mid<32>(p_h0, p_wfH, p_wfL, b_mid, p_h1, 4);
    k_conv_out<<<dim3(T_/32, B_, 3), 256>>>(p_h1, w_out, b_out,
                                            p_qh, p_ql, p_kh, p_kl, p_vth, p_vtl);

    // S = scale * Q K^T   (3xBF16 m16n8k16)
    k_mma_bf<<<dim3(T_/128, T_/128, B_), 256>>>(
        p_qh, p_ql, p_kh, p_kl, p_attn, E_,
        (size_t)T_*E_, (size_t)T_*E_, (size_t)T_*T_, T_, 0.0625f);
    k_softmax<<<B_*T_, 256>>>(p_attn, p_ph, p_pl);
    // O = P V   (same NT kernel; V pre-transposed)
    k_mma_bf<<<dim3(T_/128, E_/128, B_), 256>>>(
        p_ph, p_pl, p_vth, p_vtl, p_o, T_,
        (size_t)T_*T_, (size_t)E_*T_, (size_t)T_*E_, E_, 1.0f);
    k_final<<<B_*T_, 256>>>(p_o, out_w, out_b, rw, rb, (float*)d_out);
}

// round 17
// speedup vs baseline: 2.3328x; 1.0125x over previous
#include <cuda_runtime.h>
#include <cuda_bf16.h>
#include <math.h>
#include <stdint.h>

#define B_  8
#define T_  2048
#define C_  3
#define E_  256
#define K_  15
#define D_  5
#define BN_ 32
#define WSZ (BN_*BN_*K_)   // 15360 floats per mid layer

struct P3 { const float *q, *k, *v; };

__device__ __forceinline__ const float* pick(const P3& p, int net){
    return net==0 ? p.q : (net==1 ? p.k : p.v);
}

typedef __nv_bfloat16 bf16;

// ---------------- scratch (device globals; no allocs allowed) ----------------
static __device__ float g_mean[B_*C_];
static __device__ float g_std [B_*C_];
static __device__ float g_qn[B_*C_*T_];
static __device__ float g_kn[B_*C_*T_];
static __device__ float g_h0[3*B_*BN_*T_];
static __device__ float g_h1[3*B_*BN_*T_];
// pre-fragmented mid-conv weights (mma A-fragment layout), bf16 hi/lo words
static __device__ __align__(16) unsigned g_wfH[3*D_*15*2*2*32*4];
static __device__ __align__(16) unsigned g_wfL[3*D_*15*2*2*32*4];
static __device__ __align__(16) bf16 g_qh[(size_t)B_*T_*E_];
static __device__ __align__(16) bf16 g_ql[(size_t)B_*T_*E_];
static __device__ __align__(16) bf16 g_kh[(size_t)B_*T_*E_];
static __device__ __align__(16) bf16 g_kl[(size_t)B_*T_*E_];
static __device__ __align__(16) bf16 g_vth[(size_t)B_*E_*T_];  // V^T [B][E][T]
static __device__ __align__(16) bf16 g_vtl[(size_t)B_*E_*T_];
static __device__ float g_attn[(size_t)B_*T_*T_];              // S raw (128 MiB)
static __device__ __align__(16) bf16 g_ph[(size_t)B_*T_*T_];   // P split hi
static __device__ __align__(16) bf16 g_pl[(size_t)B_*T_*T_];   // P split lo
static __device__ float g_o[(size_t)B_*T_*E_];

// ---------------- bf16 split ----------------
__device__ __forceinline__ void bfsplit(float x, bf16& h, bf16& l){
    h = __float2bfloat16_rn(x);
    l = __float2bfloat16_rn(x - __bfloat162float(h));
}

// ---------------- RevIN stats over time of key_in ----------------
__global__ void k_stats(const float* __restrict__ key){
    int bc = blockIdx.x, b = bc / C_, c = bc % C_;
    int tid = threadIdx.x;
    float s = 0.f, ss = 0.f;
    for (int t = tid; t < T_; t += 256){
        float x = key[((size_t)b*T_ + t)*C_ + c];
        s += x; ss += x*x;
    }
    __shared__ float r1[256], r2[256];
    r1[tid]=s; r2[tid]=ss; __syncthreads();
    for(int o=128;o;o>>=1){ if(tid<o){ r1[tid]+=r1[tid+o]; r2[tid]+=r2[tid+o]; } __syncthreads(); }
    if(tid==0){
        float m = r1[0]/(float)T_;
        float v = r2[0]/(float)T_ - m*m;
        g_mean[bc]=m;
        g_std[bc]=sqrtf(v + 1e-5f);
    }
}

// ---------------- normalize + transpose to [B][C][T] ----------------
__global__ void k_norm(const float* __restrict__ q, const float* __restrict__ k,
                       const float* __restrict__ rw, const float* __restrict__ rb){
    int i = blockIdx.x*256 + threadIdx.x;
    if(i >= B_*C_*T_) return;
    int t = i % T_, c = (i / T_) % C_, b = i / (C_*T_);
    float m = g_mean[b*C_+c], inv = 1.f/g_std[b*C_+c];
    float w = rw[c], bb = rb[c];
    size_t src = ((size_t)b*T_ + t)*C_ + c;
    g_qn[i] = (q[src]-m)*inv*w + bb;
    g_kn[i] = (k[src]-m)*inv*w + bb;
}

// ------ pre-fragment mid weights into mma A layout (bf16 hi/lo words) ------
__global__ void k_wfrag(P3 wm, unsigned* __restrict__ wfH, unsigned* __restrict__ wfL){
    int k = blockIdx.x, layer = blockIdx.y, net = blockIdx.z;
    int tid = threadIdx.x;
    int lane = tid & 31, wid = tid >> 5;
    int mt = wid >> 1, cc = wid & 1;
    int lq = lane >> 2, lr = lane & 3;
    const float* w = pick(wm, net) + (size_t)layer*WSZ;  // [cout][ci][k]
    int r0 = mt*16 + lq, r1 = r0 + 8;
    int cb = cc*16 + 2*lr;
    int rows[4] = {r0, r1, r0, r1};
    int cols[4] = {cb, cb, cb+8, cb+8};
    unsigned hw[4], lw[4];
    #pragma unroll
    for(int j=0;j<4;j++){
        float v0 = w[(rows[j]*32 + cols[j])*15 + k];
        float v1 = w[(rows[j]*32 + cols[j]+1)*15 + k];
        bf16 h0,l0,h1,l1;
        bfsplit(v0,h0,l0); bfsplit(v1,h1,l1);
        hw[j] = (unsigned)__bfloat16_as_ushort(h0) | ((unsigned)__bfloat16_as_ushort(h1)<<16);
        lw[j] = (unsigned)__bfloat16_as_ushort(l0) | ((unsigned)__bfloat16_as_ushort(l1)<<16);
    }
    int idx = ((((net*D_ + layer)*15 + k)*2 + mt)*2 + cc)*32 + lane;
    ((uint4*)wfH)[idx] = make_uint4(hw[0],hw[1],hw[2],hw[3]);
    ((uint4*)wfL)[idx] = make_uint4(lw[0],lw[1],lw[2],lw[3]);
}

// ---------------- conv in (fused q/k/v): C_ -> BN_, K=15, dil=1, relu ------
__global__ void k_conv_in(const float* __restrict__ qn, const float* __restrict__ kn,
                          P3 w, P3 bias, float* __restrict__ dstbase){
    int net = blockIdx.z;
    const float* src = (net==0) ? qn : kn;
    const float* wp  = pick(w, net);
    const float* bp  = pick(bias, net);
    float* dst = dstbase + (size_t)net*B_*BN_*T_;

    __shared__ float ws[BN_*C_*K_];
    __shared__ float bs[BN_];
    __shared__ float xs[C_][256 + K_ - 1];
    int b = blockIdx.y, t0 = blockIdx.x*256, tid = threadIdx.x;
    for(int i=tid;i<BN_*C_*K_;i+=256) ws[i]=wp[i];
    if(tid<BN_) bs[tid]=bp[tid];
    const int W = 256 + K_ - 1;
    for(int i=tid;i<C_*W;i+=256){
        int ci=i/W, p=i%W, g=t0+p-7;
        xs[ci][p] = ((unsigned)g < T_) ? src[(b*C_+ci)*T_ + g] : 0.f;
    }
    __syncthreads();
    float acc[BN_];
    #pragma unroll
    for(int c=0;c<BN_;c++) acc[c]=bs[c];
    #pragma unroll
    for(int ci=0;ci<C_;ci++){
        #pragma unroll
        for(int k=0;k<K_;k++){
            float x = xs[ci][tid+k];
            #pragma unroll
            for(int c=0;c<BN_;c++) acc[c] += x * ws[(c*C_+ci)*K_+k];
        }
    }
    int t = t0 + tid;
    #pragma unroll
    for(int c=0;c<BN_;c++) dst[((size_t)b*BN_+c)*T_ + t] = fmaxf(acc[c], 0.f);
}

// ------ conv mid via tensor cores: 3xBF16 m16n8k16, dilated-shift B ------
// Block: 256 thr = 8 warps = (mt: 2 x 16-cout) x (nq: 4 x 64-t). Output 32x256.
// x tile staged t-major [t][ci] bf16 hi/lo, pitch 36 bf16; 2-ci packed stores.
template<int DIL>
__global__ void __launch_bounds__(256)
k_conv_mma(const float* __restrict__ srcbase, const unsigned* __restrict__ wfH,
           const unsigned* __restrict__ wfL, P3 bm,
           float* __restrict__ dstbase, int layer){
    constexpr int TW  = 256 + 14*DIL;
    constexpr int H   = 7*DIL;
    constexpr int RPB = 36;                // bf16 per staged row (32 + pad)
    extern __shared__ bf16 xsm[];
    bf16* xh = xsm;
    bf16* xl = xsm + TW*RPB;

    int net = blockIdx.z, b = blockIdx.y, t0 = blockIdx.x*256, tid = threadIdx.x;
    const float* src = srcbase + ((size_t)net*B_ + b)*BN_*T_;
    float* dst       = dstbase + ((size_t)net*B_ + b)*BN_*T_;

    // stage x tile: 2 adjacent ci per thread -> packed 4B stores
    for(int i=tid; i<(BN_/2)*TW; i+=256){
        int ci = (i / TW)*2, p = i - (ci>>1)*TW;
        int g = t0 - H + p;
        float v0 = 0.f, v1 = 0.f;
        if((unsigned)g < T_){
            v0 = src[ci*T_ + g];
            v1 = src[(ci+1)*T_ + g];
        }
        bf16 h0,l0,h1,l1;
        bfsplit(v0,h0,l0); bfsplit(v1,h1,l1);
        unsigned hw = (unsigned)__bfloat16_as_ushort(h0) | ((unsigned)__bfloat16_as_ushort(h1)<<16);
        unsigned lw = (unsigned)__bfloat16_as_ushort(l0) | ((unsigned)__bfloat16_as_ushort(l1)<<16);
        *(unsigned*)(xh + p*RPB + ci) = hw;
        *(unsigned*)(xl + p*RPB + ci) = lw;
    }
    __syncthreads();

    int lane = tid & 31, wid = tid >> 5;
    int mt = wid >> 2, nq = wid & 3;
    int lq = lane >> 2, lr = lane & 3;

    float acc[8][4] = {};
    int nl = (net*D_ + layer)*15;
    const uint4* fH = (const uint4*)wfH;
    const uint4* fL = (const uint4*)wfL;

    for(int k=0; k<K_; k++){
        int fi = (nl + k)*4 + mt*2;
        uint4 ah0 = __ldg(&fH[(fi+0)*32 + lane]);
        uint4 al0 = __ldg(&fL[(fi+0)*32 + lane]);
        uint4 ah1 = __ldg(&fH[(fi+1)*32 + lane]);
        uint4 al1 = __ldg(&fL[(fi+1)*32 + lane]);
        int rbase = nq*64 + lq + k*DIL;
        #pragma unroll
        for(int cc=0; cc<2; cc++){
            const unsigned* Ah = cc ? (const unsigned*)&ah1 : (const unsigned*)&ah0;
            const unsigned* Al = cc ? (const unsigned*)&al1 : (const unsigned*)&al0;
            #pragma unroll
            for(int n=0;n<8;n++){
                const bf16* rh = xh + (rbase + n*8)*RPB + cc*16;
                const bf16* rl = xl + (rbase + n*8)*RPB + cc*16;
                unsigned bh0 = *(const unsigned*)(rh + 2*lr);
                unsigned bh1 = *(const unsigned*)(rh + 2*lr + 8);
                unsigned bl0 = *(const unsigned*)(rl + 2*lr);
                unsigned bl1 = *(const unsigned*)(rl + 2*lr + 8);
                asm volatile(
                    "mma.sync.aligned.m16n8k16.row.col.f32.bf16.bf16.f32 "
                    "{%0,%1,%2,%3},{%4,%5,%6,%7},{%8,%9},{%0,%1,%2,%3};"
                    : "+f"(acc[n][0]), "+f"(acc[n][1]), "+f"(acc[n][2]), "+f"(acc[n][3])
                    : "r"(Ah[0]), "r"(Ah[1]), "r"(Ah[2]), "r"(Ah[3]), "r"(bh0), "r"(bh1));
                asm volatile(
                    "mma.sync.aligned.m16n8k16.row.col.f32.bf16.bf16.f32 "
                    "{%0,%1,%2,%3},{%4,%5,%6,%7},{%8,%9},{%0,%1,%2,%3};"
                    : "+f"(acc[n][0]), "+f"(acc[n][1]), "+f"(acc[n][2]), "+f"(acc[n][3])
                    : "r"(Ah[0]), "r"(Ah[1]), "r"(Ah[2]), "r"(Ah[3]), "r"(bl0), "r"(bl1));
                asm volatile(
                    "mma.sync.aligned.m16n8k16.row.col.f32.bf16.bf16.f32 "
                    "{%0,%1,%2,%3},{%4,%5,%6,%7},{%8,%9},{%0,%1,%2,%3};"
                    : "+f"(acc[n][0]), "+f"(acc[n][1]), "+f"(acc[n][2]), "+f"(acc[n][3])
                    : "r"(Al[0]), "r"(Al[1]), "r"(Al[2]), "r"(Al[3]), "r"(bh0), "r"(bh1));
            }
        }
    }

    const float* bias = pick(bm, net) + layer*BN_ + mt*16;
    float b0 = __ldg(&bias[lq]), b1 = __ldg(&bias[lq+8]);
    int r0 = mt*16 + lq, r1 = r0 + 8;
    #pragma unroll
    for(int n=0;n<8;n++){
        int t = t0 + nq*64 + n*8 + 2*lr;
        float2 v0 = make_float2(fmaxf(acc[n][0]+b0,0.f), fmaxf(acc[n][1]+b0,0.f));
        float2 v1 = make_float2(fmaxf(acc[n][2]+b1,0.f), fmaxf(acc[n][3]+b1,0.f));
        *(float2*)(dst + (size_t)r0*T_ + t) = v0;
        *(float2*)(dst + (size_t)r1*T_ + t) = v1;
    }
}

// ------- conv out (fused, 1x1): BN_ -> E_, writes bf16-split Q/K/Vt -------
__global__ void k_conv_out(const float* __restrict__ srcbase, P3 w, P3 bias,
                           bf16* __restrict__ qh, bf16* __restrict__ ql,
                           bf16* __restrict__ kh, bf16* __restrict__ kl,
                           bf16* __restrict__ vth, bf16* __restrict__ vtl){
    int net = blockIdx.z;
    const float* src = srcbase + (size_t)net*B_*BN_*T_;
    const float* wp  = pick(w, net);
    const float* bp  = pick(bias, net);

    __shared__ float xs[BN_][32];
    int b = blockIdx.y, t0 = blockIdx.x*32, e = threadIdx.x;
    for(int i=e;i<BN_*32;i+=256){
        int ci=i>>5, tl=i&31;
        xs[ci][tl] = src[((size_t)b*BN_+ci)*T_ + t0 + tl];
    }
    __syncthreads();
    float acc[32];
    float bb = bp[e];
    #pragma unroll
    for(int t=0;t<32;t++) acc[t]=bb;
    #pragma unroll 4
    for(int ci=0;ci<BN_;ci++){
        float wv = __ldg(&wp[e*BN_+ci]);
        #pragma unroll
        for(int t=0;t<32;t++) acc[t] += xs[ci][t]*wv;
    }
    if(net < 2){
        bf16* H = net ? kh : qh;
        bf16* L = net ? kl : ql;
        #pragma unroll
        for(int t=0;t<32;t++){
            bf16 h,l; bfsplit(acc[t], h, l);
            size_t o = ((size_t)b*T_ + t0+t)*E_ + e;
            H[o]=h; L[o]=l;
        }
    } else {
        size_t o = ((size_t)b*E_ + e)*T_ + t0;
        #pragma unroll
        for(int t=0;t<32;t++){
            bf16 h,l; bfsplit(acc[t], h, l);
            vth[o+t]=h; vtl[o+t]=l;
        }
    }
}

// =========== 3xBF16 mma.sync m16n8k16 GEMM, NT form, bf16-split inputs =====
__device__ __forceinline__ void mma16(float* c, const unsigned* a, unsigned b0, unsigned b1){
    asm volatile(
        "mma.sync.aligned.m16n8k16.row.col.f32.bf16.bf16.f32 "
        "{%0,%1,%2,%3},{%4,%5,%6,%7},{%8,%9},{%0,%1,%2,%3};"
        : "+f"(c[0]), "+f"(c[1]), "+f"(c[2]), "+f"(c[3])
        : "r"(a[0]), "r"(a[1]), "r"(a[2]), "r"(a[3]), "r"(b0), "r"(b1));
}

#define SKM 136   // padded leading dim (words)

__device__ __forceinline__ void mma_chunk_bf(
    const unsigned (*AsH)[SKM], const unsigned (*AsL)[SKM],
    const unsigned (*BsH)[SKM], const unsigned (*BsL)[SKM],
    float acc[16][4], int wm, int wn, int lane)
{
    int lq = lane >> 2, lr = lane & 3;
    unsigned aH[2][4], aL[2][4];
    #pragma unroll
    for(int mt=0; mt<2; mt++){
        int rm = wm*32 + mt*16 + lq;
        aH[mt][0]=AsH[lr  ][rm];  aH[mt][1]=AsH[lr  ][rm+8];
        aH[mt][2]=AsH[lr+4][rm];  aH[mt][3]=AsH[lr+4][rm+8];
        aL[mt][0]=AsL[lr  ][rm];  aL[mt][1]=AsL[lr  ][rm+8];
        aL[mt][2]=AsL[lr+4][rm];  aL[mt][3]=AsL[lr+4][rm+8];
    }
    #pragma unroll
    for(int nt=0; nt<8; nt++){
        int cn = wn*64 + nt*8 + lq;
        unsigned bH0=BsH[lr][cn], bH1=BsH[lr+4][cn];
        unsigned bL0=BsL[lr][cn], bL1=BsL[lr+4][cn];
        #pragma unroll
        for(int mt=0; mt<2; mt++){
            mma16(acc[mt*8+nt], aH[mt], bH0, bH1);
            mma16(acc[mt*8+nt], aH[mt], bL0, bL1);
            mma16(acc[mt*8+nt], aL[mt], bH0, bH1);
        }
    }
}

// C[M,N] = alpha * A[M,K] * B[N,K]^T, A/B as bf16 hi/lo arrays (K contiguous)
__global__ void __launch_bounds__(256, 2)
k_mma_bf(const bf16* __restrict__ Ah, const bf16* __restrict__ Al,
         const bf16* __restrict__ Bh, const bf16* __restrict__ Bl,
         float* __restrict__ Cm, int Kdim,
         size_t sA, size_t sB, size_t sC, int ldC, float alpha){
    __shared__ unsigned AsH[8][SKM], AsL[8][SKM], BsH[8][SKM], BsL[8][SKM];
    int bz = blockIdx.z;
    Ah += bz*sA; Al += bz*sA;
    Bh += bz*sB; Bl += bz*sB;
    Cm += bz*sC;
    int tid = threadIdx.x, lane = tid & 31, wid = tid >> 5;
    int wm = wid & 3, wn = wid >> 2;
    int row0 = blockIdx.x*128, col0 = blockIdx.y*128;

    float acc[16][4];
    #pragma unroll
    for(int i=0;i<16;i++){ acc[i][0]=acc[i][1]=acc[i][2]=acc[i][3]=0.f; }

    int r = tid >> 1, w4 = (tid & 1) * 4;
    const unsigned* wAh = (const unsigned*)(Ah + (size_t)(row0+r)*Kdim);
    const unsigned* wAl = (const unsigned*)(Al + (size_t)(row0+r)*Kdim);
    const unsigned* wBh = (const unsigned*)(Bh + (size_t)(col0+r)*Kdim);
    const unsigned* wBl = (const unsigned*)(Bl + (size_t)(col0+r)*Kdim);

    uint4 vah, val_, vbh, vbl;
    vah = *(const uint4*)(wAh + w4);
    val_ = *(const uint4*)(wAl + w4);
    vbh = *(const uint4*)(wBh + w4);
    vbl = *(const uint4*)(wBl + w4);

    const int NCH = Kdim >> 4;
    for(int ch=0; ch<NCH; ch++){
        AsH[w4+0][r]=vah.x; AsH[w4+1][r]=vah.y; AsH[w4+2][r]=vah.z; AsH[w4+3][r]=vah.w;
        AsL[w4+0][r]=val_.x; AsL[w4+1][r]=val_.y; AsL[w4+2][r]=val_.z; AsL[w4+3][r]=val_.w;
        BsH[w4+0][r]=vbh.x; BsH[w4+1][r]=vbh.y; BsH[w4+2][r]=vbh.z; BsH[w4+3][r]=vbh.w;
        BsL[w4+0][r]=vbl.x; BsL[w4+1][r]=vbl.y; BsL[w4+2][r]=vbl.z; BsL[w4+3][r]=vbl.w;
        __syncthreads();
        if(ch+1 < NCH){
            int wo = (ch+1)*8 + w4;
            vah = *(const uint4*)(wAh + wo);
            val_ = *(const uint4*)(wAl + wo);
            vbh = *(const uint4*)(wBh + wo);
            vbl = *(const uint4*)(wBl + wo);
        }
        mma_chunk_bf(AsH, AsL, BsH, BsL, acc, wm, wn, lane);
        __syncthreads();
    }
    int lq = lane>>2, lr = lane&3;
    #pragma unroll
    for(int mt=0; mt<2; mt++){
        #pragma unroll
        for(int nt=0; nt<8; nt++){
            int row = row0 + wm*32 + mt*16 + lq;
            int col = col0 + wn*64 + nt*8 + lr*2;
            float* c = acc[mt*8+nt];
            *(float2*)(Cm + (size_t)row*ldC + col)     = make_float2(c[0]*alpha, c[1]*alpha);
            *(float2*)(Cm + (size_t)(row+8)*ldC + col) = make_float2(c[2]*alpha, c[3]*alpha);
        }
    }
}

// ---------------- row softmax over T_, writes bf16-split P ----------------
__global__ void k_softmax(const float* __restrict__ S, bf16* __restrict__ PH,
                          bf16* __restrict__ PL){
    size_t row = blockIdx.x;
    const float* p = S + row*T_;
    int tid = threadIdx.x;
    float v[8];
    #pragma unroll
    for(int j=0;j<8;j++) v[j] = p[tid + j*256];
    float m = v[0];
    #pragma unroll
    for(int j=1;j<8;j++) m = fmaxf(m, v[j]);
    __shared__ float sm[40];
    for(int o=16;o;o>>=1) m = fmaxf(m, __shfl_xor_sync(0xffffffffu, m, o));
    if((tid&31)==0) sm[tid>>5] = m;
    __syncthreads();
    if(tid<32){
        float t = (tid<8)?sm[tid]:-3.0e38f;
        for(int o=4;o;o>>=1) t=fmaxf(t,__shfl_xor_sync(0xffffffffu,t,o));
        if(tid==0) sm[32]=t;
    }
    __syncthreads();
    m = sm[32];
    float s=0.f;
    #pragma unroll
    for(int j=0;j<8;j++){ v[j]=__expf(v[j]-m); s+=v[j]; }
    for(int o=16;o;o>>=1) s += __shfl_xor_sync(0xffffffffu, s, o);
    if((tid&31)==0) sm[tid>>5] = s;
    __syncthreads();
    if(tid<32){
        float t=(tid<8)?sm[tid]:0.f;
        for(int o=4;o;o>>=1) t+=__shfl_xor_sync(0xffffffffu,t,o);
        if(tid==0) sm[33]=t;
    }
    __syncthreads();
    float inv = 1.f/sm[33];
    size_t off = row*T_ + tid;
    #pragma unroll
    for(int j=0;j<8;j++){
        float pv = v[j]*inv;
        bf16 h,l; bfsplit(pv, h, l);
        PH[off + j*256] = h;
        PL[off + j*256] = l;
    }
}

// ---------------- output proj + RevIN denorm ----------------
__global__ void k_final(const float* __restrict__ o, const float* __restrict__ w,
                        const float* __restrict__ ob, const float* __restrict__ rw,
                        const float* __restrict__ rb, float* __restrict__ out){
    int bt = blockIdx.x;
    int b  = bt >> 11;
    int e  = threadIdx.x;
    float x = o[(size_t)bt*E_ + e];
    float p0 = x*w[e], p1 = x*w[E_+e], p2 = x*w[2*E_+e];
    for(int s=16;s;s>>=1){
        p0 += __shfl_down_sync(0xffffffffu, p0, s);
        p1 += __shfl_down_sync(0xffffffffu, p1, s);
        p2 += __shfl_down_sync(0xffffffffu, p2, s);
    }
    __shared__ float sm[3][8];
    int wid=e>>5, lane=e&31;
    if(lane==0){ sm[0][wid]=p0; sm[1][wid]=p1; sm[2][wid]=p2; }
    __syncthreads();
    if(e < C_){
        float s=0.f;
        #pragma unroll
        for(int wdx=0;wdx<8;wdx++) s += sm[e][wdx];
        int c = e;
        float val = s + ob[c];
        val = (val - rb[c]) / rw[c];
        val = val * g_std[b*C_+c] + g_mean[b*C_+c];
        out[(size_t)bt*C_ + c] = val;
    }
}

// ---------------- host orchestration (graph-capturable) ----------------
template<int DIL>
static void launch_mid(const float* src, const unsigned* wfH, const unsigned* wfL,
                       P3 bm, float* dst, int layer){
    constexpr int TW = 256 + 14*DIL;
    size_t smem = (size_t)TW * 36 * 2 * sizeof(bf16);   // xh + xl
    cudaFuncSetAttribute(k_conv_mma<DIL>, cudaFuncAttributeMaxDynamicSharedMemorySize, (int)smem);
    k_conv_mma<DIL><<<dim3(T_/256, B_, 3), 256, smem>>>(src, wfH, wfL, bm, dst, layer);
}

extern "C" void kernel_launch(void* const* d_in, const int* in_sizes, int n_in,
                              void* d_out, int out_size){
    const float* query = (const float*)d_in[0];
    const float* key   = (const float*)d_in[1];
    const float* out_w = (const float*)d_in[20];
    const float* out_b = (const float*)d_in[21];
    const float* rw    = (const float*)d_in[22];
    const float* rb    = (const float*)d_in[23];

    float *p_qn,*p_kn,*p_h0,*p_h1,*p_attn,*p_o;
    unsigned *p_wfH,*p_wfL;
    bf16 *p_qh,*p_ql,*p_kh,*p_kl,*p_vth,*p_vtl,*p_ph,*p_pl;
    cudaGetSymbolAddress((void**)&p_qn,   g_qn);
    cudaGetSymbolAddress((void**)&p_kn,   g_kn);
    cudaGetSymbolAddress((void**)&p_h0,   g_h0);
    cudaGetSymbolAddress((void**)&p_h1,   g_h1);
    cudaGetSymbolAddress((void**)&p_wfH,  g_wfH);
    cudaGetSymbolAddress((void**)&p_wfL,  g_wfL);
    cudaGetSymbolAddress((void**)&p_qh,   g_qh);
    cudaGetSymbolAddress((void**)&p_ql,   g_ql);
    cudaGetSymbolAddress((void**)&p_kh,   g_kh);
    cudaGetSymbolAddress((void**)&p_kl,   g_kl);
    cudaGetSymbolAddress((void**)&p_vth,  g_vth);
    cudaGetSymbolAddress((void**)&p_vtl,  g_vtl);
    cudaGetSymbolAddress((void**)&p_attn, g_attn);
    cudaGetSymbolAddress((void**)&p_ph,   g_ph);
    cudaGetSymbolAddress((void**)&p_pl,   g_pl);
    cudaGetSymbolAddress((void**)&p_o,    g_o);

    P3 w_in  = {(const float*)d_in[2],  (const float*)d_in[8],  (const float*)d_in[14]};
    P3 b_in  = {(const float*)d_in[3],  (const float*)d_in[9],  (const float*)d_in[15]};
    P3 w_mid = {(const float*)d_in[4],  (const float*)d_in[10], (const float*)d_in[16]};
    P3 b_mid = {(const float*)d_in[5],  (const float*)d_in[11], (const float*)d_in[17]};
    P3 w_out = {(const float*)d_in[6],  (const float*)d_in[12], (const float*)d_in[18]};
    P3 b_out = {(const float*)d_in[7],  (const float*)d_in[13], (const float*)d_in[19]};

    k_stats<<<B_*C_, 256>>>(key);
    k_norm<<<(B_*C_*T_ + 255)/256, 256>>>(query, key, rw, rb);
    k_wfrag<<<dim3(15, D_, 3), 128>>>(w_mid, p_wfH, p_wfL);

    k_conv_in<<<dim3(T_/256, B_, 3), 256>>>(p_qn, p_kn, w_in, b_in, p_h0);
    launch_mid<2 >(p_h0, p_wfH, p_wfL, b_mid, p_h1, 0);
    launch_mid<4 >(p_h1, p_wfH, p_wfL, b_mid, p_h0, 1);
    launch_mid<8 >(p_h0, p_wfH, p_wfL, b_mid, p_h1, 2);
    launch_mid<16>(p_h1, p_wfH, p_wfL, b_mid, p_h0, 3);
    launch_mid<32>(p_h0, p_wfH, p_wfL, b_mid, p_h1, 4);
    k_conv_out<<<dim3(T_/32, B_, 3), 256>>>(p_h1, w_out, b_out,
                                            p_qh, p_ql, p_kh, p_kl, p_vth, p_vtl);

    // S = scale * Q K^T   (3xBF16 m16n8k16)
    k_mma_bf<<<dim3(T_/128, T_/128, B_), 256>>>(
        p_qh, p_ql, p_kh, p_kl, p_attn, E_,
        (size_t)T_*E_, (size_t)T_*E_, (size_t)T_*T_, T_, 0.0625f);
    k_softmax<<<B_*T_, 256>>>(p_attn, p_ph, p_pl);
    // O = P V   (same NT kernel; V pre-transposed)
    k_mma_bf<<<dim3(T_/128, E_/128, B_), 256>>>(
        p_ph, p_pl, p_vth, p_vtl, p_o, T_,
        (size_t)T_*T_, (size_t)E_*T_, (size_t)T_*E_, E_, 1.0f);
    k_final<<<B_*T_, 256>>>(p_o, out_w, out_b, rw, rb, (float*)d_out);
}